// round 9
// baseline (speedup 1.0000x reference)
#include <cuda_runtime.h>
#include <cuda_bf16.h>
#include <math.h>
#include <cstdint>

using bf16 = __nv_bfloat16;

static constexpr int L_ = 6, D_ = 1024, H_ = 16, F_ = 4096, S_ = 512, B_ = 16, P_ = 512;
static constexpr int DH_ = D_ / H_;
static constexpr int M_ = B_ * S_;
static constexpr int D3 = 3 * D_;

// ---------------- scratch ----------------------------------------------------
__device__ __align__(16) float g_h[(size_t)M_ * D_];
__device__ __align__(16) float g_out1[(size_t)M_ * D_];
__device__ __align__(16) float g_ctx32[(size_t)M_ * D_];
__device__ __align__(16) float g_f132[(size_t)M_ * F_];

__device__ __align__(16) bf16   g_xn_h[(size_t)M_ * D_];
__device__ __align__(16) int8_t g_xn_hq[(size_t)M_ * D_];
__device__ __align__(16) int8_t g_xn_lq[(size_t)M_ * D_];
__device__ __align__(16) float  g_xn_s[M_];
__device__ __align__(16) bf16   g_cx_h[(size_t)M_ * D_];
__device__ __align__(16) int8_t g_cx_hq[(size_t)M_ * D_];
__device__ __align__(16) int8_t g_cx_lq[(size_t)M_ * D_];
__device__ __align__(16) float  g_cx_s[M_];
__device__ __align__(16) bf16   g_f1_h[(size_t)M_ * F_];
__device__ __align__(16) int8_t g_f1_hq[(size_t)M_ * F_];
__device__ __align__(16) int8_t g_f1_lq[(size_t)M_ * F_];
__device__ __align__(16) float  g_f1_s[M_];

__device__ __align__(16) bf16 g_qkv_h[(size_t)M_ * D3];
__device__ __align__(16) bf16 g_qkv_l[(size_t)M_ * D3];

__device__ __align__(16) bf16   g_wqkv_bf[(size_t)L_ * D3 * D_];
__device__ __align__(16) int8_t g_wqkv_hq[(size_t)L_ * D3 * D_];
__device__ __align__(16) int8_t g_wqkv_lq[(size_t)L_ * D3 * D_];
__device__ __align__(16) float  g_wqkv_s[(size_t)L_ * D3];
__device__ __align__(16) bf16   g_wo_bf[(size_t)L_ * D_ * D_];
__device__ __align__(16) int8_t g_wo_hq[(size_t)L_ * D_ * D_];
__device__ __align__(16) int8_t g_wo_lq[(size_t)L_ * D_ * D_];
__device__ __align__(16) float  g_wo_s[(size_t)L_ * D_];
__device__ __align__(16) bf16   g_w1_bf[(size_t)L_ * D_ * F_];
__device__ __align__(16) int8_t g_w1_hq[(size_t)L_ * D_ * F_];
__device__ __align__(16) int8_t g_w1_lq[(size_t)L_ * D_ * F_];
__device__ __align__(16) float  g_w1_s[(size_t)L_ * F_];
__device__ __align__(16) bf16   g_w2_bf[(size_t)L_ * F_ * D_];
__device__ __align__(16) int8_t g_w2_hq[(size_t)L_ * F_ * D_];
__device__ __align__(16) int8_t g_w2_lq[(size_t)L_ * F_ * D_];
__device__ __align__(16) float  g_w2_s[(size_t)L_ * D_];
__device__ __align__(16) float  g_wt32[(size_t)L_ * F_ * D_];
__device__ __align__(16) float  g_bqkv[(size_t)L_ * D3];

// ---------------- PTX helpers -------------------------------------------------
__device__ __forceinline__ uint32_t smem_u32(const void* p) {
    uint32_t a;
    asm("{ .reg .u64 t; cvta.to.shared.u64 t, %1; cvt.u32.u64 %0, t; }" : "=r"(a) : "l"(p));
    return a;
}
__device__ __forceinline__ void ldsm4(uint32_t* r, uint32_t addr) {
    asm volatile("ldmatrix.sync.aligned.m8n8.x4.shared.b16 {%0,%1,%2,%3}, [%4];"
                 : "=r"(r[0]), "=r"(r[1]), "=r"(r[2]), "=r"(r[3]) : "r"(addr));
}
__device__ __forceinline__ void ldsm4t(uint32_t* r, uint32_t addr) {
    asm volatile("ldmatrix.sync.aligned.m8n8.x4.trans.shared.b16 {%0,%1,%2,%3}, [%4];"
                 : "=r"(r[0]), "=r"(r[1]), "=r"(r[2]), "=r"(r[3]) : "r"(addr));
}
__device__ __forceinline__ void mma16816(float* d, const uint32_t* a, uint32_t b0, uint32_t b1) {
    asm volatile("mma.sync.aligned.m16n8k16.row.col.f32.bf16.bf16.f32 "
                 "{%0,%1,%2,%3}, {%4,%5,%6,%7}, {%8,%9}, {%0,%1,%2,%3};"
                 : "+f"(d[0]), "+f"(d[1]), "+f"(d[2]), "+f"(d[3])
                 : "r"(a[0]), "r"(a[1]), "r"(a[2]), "r"(a[3]), "r"(b0), "r"(b1));
}
__device__ __forceinline__ void imma16832(int* d, const uint32_t* a, uint32_t b0, uint32_t b1) {
    asm volatile("mma.sync.aligned.m16n8k32.row.col.s32.s8.s8.s32 "
                 "{%0,%1,%2,%3}, {%4,%5,%6,%7}, {%8,%9}, {%0,%1,%2,%3};"
                 : "+r"(d[0]), "+r"(d[1]), "+r"(d[2]), "+r"(d[3])
                 : "r"(a[0]), "r"(a[1]), "r"(a[2]), "r"(a[3]), "r"(b0), "r"(b1));
}
#define CPA(dst, src)  asm volatile("cp.async.cg.shared.global [%0], [%1], 16;" :: "r"(dst), "l"(src))
#define CPA_COMMIT()   asm volatile("cp.async.commit_group;" ::: "memory")
#define CPA_WAIT1()    asm volatile("cp.async.wait_group 1;" ::: "memory")
#define CPA_WAIT0()    asm volatile("cp.async.wait_group 0;" ::: "memory")

__device__ __forceinline__ uint32_t swz(uint32_t off)   { return off ^ ((off >> 3) & 0x70); }
__device__ __forceinline__ uint32_t swz64(uint32_t off) { return off ^ ((off >> 3) & 0x30); }
__device__ __forceinline__ uint32_t smx(uint32_t r, uint32_t c)   { return r + (c ^ ((r >> 3) & 0x70)); }
__device__ __forceinline__ uint32_t smx64(uint32_t r, uint32_t c) { return r + (c ^ ((r >> 3) & 0x30)); }
__device__ __forceinline__ int8_t q8(float v) {
    int i = __float2int_rn(v);
    return (int8_t)max(-127, min(127, i));
}

// ---------------- small kernels ----------------------------------------------
__global__ __launch_bounds__(256) void addpe_kernel(const float* __restrict__ x,
                                                    const float* __restrict__ pe,
                                                    float* __restrict__ h) {
    int i = blockIdx.x * 256 + threadIdx.x;
    h[i] = x[i] + pe[i & (S_ * D_ - 1)];
}

__global__ __launch_bounds__(256) void packb_kernel(const float* __restrict__ bq,
                                                    const float* __restrict__ bk,
                                                    const float* __restrict__ bv,
                                                    float* __restrict__ o) {
    int l = blockIdx.y;
    int i = blockIdx.x * 256 + threadIdx.x;
    o[(size_t)l * D3 + i]          = bq[l * D_ + i];
    o[(size_t)l * D3 + D_ + i]     = bk[l * D_ + i];
    o[(size_t)l * D3 + 2 * D_ + i] = bv[l * D_ + i];
}

// fp32 transpose W[K,N] -> T[N,K]
__global__ __launch_bounds__(256) void wtransf32_kernel(const float* __restrict__ W,
                                                        float* __restrict__ T,
                                                        int K, int N, size_t out_ls, int row_off) {
    __shared__ float t[32][33];
    size_t inoff  = (size_t)blockIdx.z * K * N;
    size_t outoff = (size_t)blockIdx.z * out_ls;
    int k0 = blockIdx.y * 32, n0 = blockIdx.x * 32;
    int tx = threadIdx.x & 31, ty = threadIdx.x >> 5;
#pragma unroll
    for (int i = 0; i < 32; i += 8)
        t[ty + i][tx] = W[inoff + (size_t)(k0 + ty + i) * N + n0 + tx];
    __syncthreads();
#pragma unroll
    for (int i = 0; i < 32; i += 8)
        T[outoff + (size_t)(row_off + n0 + ty + i) * K + k0 + tx] = t[tx][ty + i];
}

// fp32 [rows,K] -> bf16 plane + int8 hi/lo planes + per-row scale
__global__ __launch_bounds__(256) void rowquant_kernel(
    const float* __restrict__ X, bf16* __restrict__ yh,
    int8_t* __restrict__ yhq, int8_t* __restrict__ ylq,
    float* __restrict__ s, int K) {
    int row = blockIdx.x, tid = threadIdx.x;
    const float* xr = X + (size_t)row * K;
    int iters = K >> 10;
    float xv[16], hf[16];
    float mx = 0.f;
    for (int it = 0; it < iters; it++) {
        float4 f = *(const float4*)(xr + it * 1024 + tid * 4);
        xv[it*4+0]=f.x; xv[it*4+1]=f.y; xv[it*4+2]=f.z; xv[it*4+3]=f.w;
#pragma unroll
        for (int j = 0; j < 4; j++) {
            hf[it*4+j] = __bfloat162float(__float2bfloat16(xv[it*4+j]));
            mx = fmaxf(mx, fabsf(hf[it*4+j]));
        }
    }
#pragma unroll
    for (int o = 16; o > 0; o >>= 1) mx = fmaxf(mx, __shfl_xor_sync(0xffffffffu, mx, o));
    __shared__ float rm[8];
    if ((tid & 31) == 0) rm[tid >> 5] = mx;
    __syncthreads();
    float mall = 0.f;
#pragma unroll
    for (int i = 0; i < 8; i++) mall = fmaxf(mall, rm[i]);
    float sc = fmaxf(mall, 1e-20f) * (1.f / 127.f);
    float inv = 1.f / sc, inv2 = inv * 256.f;
    for (int it = 0; it < iters; it++) {
        size_t base = (size_t)row * K + it * 1024 + tid * 4;
#pragma unroll
        for (int j = 0; j < 4; j += 2)
            *(__nv_bfloat162*)(yh + base + j) = __nv_bfloat162(
                __float2bfloat16(xv[it*4+j]), __float2bfloat16(xv[it*4+j+1]));
        *(char4*)(yhq + base) = make_char4(q8(hf[it*4]*inv), q8(hf[it*4+1]*inv),
                                           q8(hf[it*4+2]*inv), q8(hf[it*4+3]*inv));
        *(char4*)(ylq + base) = make_char4(
            q8((xv[it*4]-hf[it*4])*inv2),   q8((xv[it*4+1]-hf[it*4+1])*inv2),
            q8((xv[it*4+2]-hf[it*4+2])*inv2), q8((xv[it*4+3]-hf[it*4+3])*inv2));
    }
    if (tid == 0) s[row] = sc;
}

// LayerNorm -> quant set
__global__ __launch_bounds__(256) void ln_kernel(const float* __restrict__ x,
                                                 const float* __restrict__ g,
                                                 const float* __restrict__ b,
                                                 bf16* __restrict__ yh,
                                                 int8_t* __restrict__ yhq,
                                                 int8_t* __restrict__ ylq,
                                                 float* __restrict__ s) {
    int row = blockIdx.x, tid = threadIdx.x;
    float4 f = *(const float4*)(x + (size_t)row * D_ + tid * 4);
    float sm = f.x + f.y + f.z + f.w;
    float ss = f.x*f.x + f.y*f.y + f.z*f.z + f.w*f.w;
#pragma unroll
    for (int o = 16; o > 0; o >>= 1) {
        sm += __shfl_xor_sync(0xffffffffu, sm, o);
        ss += __shfl_xor_sync(0xffffffffu, ss, o);
    }
    __shared__ float rs[8], rss[8], rmx[8];
    if ((tid & 31) == 0) { rs[tid >> 5] = sm; rss[tid >> 5] = ss; }
    __syncthreads();
    float ts = 0.f, tss = 0.f;
#pragma unroll
    for (int i = 0; i < 8; i++) { ts += rs[i]; tss += rss[i]; }
    float mean = ts * (1.0f / D_);
    float var  = tss * (1.0f / D_) - mean * mean;
    float r    = rsqrtf(var + 1e-6f);
    float4 g4 = *(const float4*)(g + tid * 4);
    float4 b4 = *(const float4*)(b + tid * 4);
    float o[4], hf[4];
    o[0]=(f.x-mean)*r*g4.x+b4.x; o[1]=(f.y-mean)*r*g4.y+b4.y;
    o[2]=(f.z-mean)*r*g4.z+b4.z; o[3]=(f.w-mean)*r*g4.w+b4.w;
    float mx = 0.f;
#pragma unroll
    for (int j = 0; j < 4; j++) {
        hf[j] = __bfloat162float(__float2bfloat16(o[j]));
        mx = fmaxf(mx, fabsf(hf[j]));
    }
#pragma unroll
    for (int oo = 16; oo > 0; oo >>= 1) mx = fmaxf(mx, __shfl_xor_sync(0xffffffffu, mx, oo));
    if ((tid & 31) == 0) rmx[tid >> 5] = mx;
    __syncthreads();
    float mall = 0.f;
#pragma unroll
    for (int i = 0; i < 8; i++) mall = fmaxf(mall, rmx[i]);
    float sc = fmaxf(mall, 1e-20f) * (1.f / 127.f);
    float inv = 1.f / sc, inv2 = inv * 256.f;
    size_t base = (size_t)row * D_ + tid * 4;
#pragma unroll
    for (int j = 0; j < 4; j += 2)
        *(__nv_bfloat162*)(yh + base + j) = __nv_bfloat162(
            __float2bfloat16(o[j]), __float2bfloat16(o[j+1]));
    *(char4*)(yhq + base) = make_char4(q8(hf[0]*inv), q8(hf[1]*inv), q8(hf[2]*inv), q8(hf[3]*inv));
    *(char4*)(ylq + base) = make_char4(q8((o[0]-hf[0])*inv2), q8((o[1]-hf[1])*inv2),
                                       q8((o[2]-hf[2])*inv2), q8((o[3]-hf[3])*inv2));
    if (tid == 0) s[row] = sc;
}

// ---------------- hybrid GEMM: bf16 main + int8 corrections -------------------
static constexpr int ST_AH = 0, ST_AQ = 8192, ST_BH = 16384, ST_BQ = 24576;
static constexpr int STG = 32768;
static constexpr int GEMM_SMEM = 3 * STG;   // 96 KB

__device__ __forceinline__ void stage_load(
    const bf16* __restrict__ Abf, const int8_t* __restrict__ Ahq, const int8_t* __restrict__ Alq,
    const bf16* __restrict__ Bbf, const int8_t* __restrict__ Bhq, const int8_t* __restrict__ Blq,
    int rowBase, int colBase, int KK, int k0, uint32_t st, int tid) {
    int r = tid >> 2, c = tid & 3;
    uint32_t so = swz64(r * 64 + c * 16);
    CPA(st + ST_AH + so, Abf + (size_t)(rowBase + r) * KK + k0 + c * 8);
    CPA(st + ST_AQ + so, (c < 2 ? Ahq : Alq) + (size_t)(rowBase + r) * KK + k0 + (c & 1) * 16);
    CPA(st + ST_BH + so, Bbf + (size_t)(colBase + r) * KK + k0 + c * 8);
    CPA(st + ST_BQ + so, (c < 2 ? Bhq : Blq) + (size_t)(colBase + r) * KK + k0 + (c & 1) * 16);
}

__global__ __launch_bounds__(512, 1) void gemm_mma_kernel(
    const bf16* __restrict__ Abf, const int8_t* __restrict__ Ahq,
    const int8_t* __restrict__ Alq, const float* __restrict__ sA,
    const bf16* __restrict__ Bbf, const int8_t* __restrict__ Bhq,
    const int8_t* __restrict__ Blq, const float* __restrict__ sB,
    const float* __restrict__ bias, const float* __restrict__ r1,
    const float* __restrict__ r2, float* __restrict__ C,
    bf16* __restrict__ Ch, bf16* __restrict__ Cl,
    int NN, int KK, int act) {
    extern __shared__ char smem[];
    const uint32_t sb = smem_u32(smem);
    const int tid = threadIdx.x;
    const int wid = tid >> 5, lane = tid & 31;
    const int wm = wid >> 3, wn = wid & 7;       // 2 x 8 warps; warp tile 64x16
    const int rowBase = blockIdx.y * 128, colBase = blockIdx.x * 128;

    float accF[4][2][4] = {};
    int   accI[4][2][4] = {};

    const uint32_t a_row = (uint32_t)((wm * 64 + (lane & 15)) * 64);
    const uint32_t a_col = (uint32_t)((lane >> 4) * 16);
    const uint32_t b_row = (uint32_t)((wn * 16 + (lane & 7) + ((lane >> 4) << 3)) * 64);
    const uint32_t b_col = (uint32_t)(((lane >> 3) & 1) * 16);

    const int nc = KK / 32;
    stage_load(Abf, Ahq, Alq, Bbf, Bhq, Blq, rowBase, colBase, KK, 0,  sb,       tid);
    CPA_COMMIT();
    stage_load(Abf, Ahq, Alq, Bbf, Bhq, Blq, rowBase, colBase, KK, 32, sb + STG, tid);
    CPA_COMMIT();

    for (int c = 0; c < nc; c++) {
        if (c + 1 < nc) CPA_WAIT1(); else CPA_WAIT0();
        __syncthreads();
        if (c + 2 < nc) {
            stage_load(Abf, Ahq, Alq, Bbf, Bhq, Blq, rowBase, colBase, KK,
                       (c + 2) * 32, sb + ((c + 2) % 3) * STG, tid);
            CPA_COMMIT();
        }
        uint32_t st = sb + (c % 3) * STG;

        uint32_t bf0[4], bf1[4], bqh[4], bql[4];
        ldsm4(bf0, st + ST_BH + smx64(b_row, 0  + b_col));
        ldsm4(bf1, st + ST_BH + smx64(b_row, 32 + b_col));
        ldsm4(bqh, st + ST_BQ + smx64(b_row, 0  + b_col));
        ldsm4(bql, st + ST_BQ + smx64(b_row, 32 + b_col));
#pragma unroll
        for (int mi = 0; mi < 4; mi++) {
            uint32_t ro = a_row + (uint32_t)(mi * 16 * 64);
            uint32_t af0[4], af1[4], aqh[4], aql[4];
            ldsm4(af0, st + ST_AH + smx64(ro, 0  + a_col));
            ldsm4(af1, st + ST_AH + smx64(ro, 32 + a_col));
            ldsm4(aqh, st + ST_AQ + smx64(ro, 0  + a_col));
            ldsm4(aql, st + ST_AQ + smx64(ro, 32 + a_col));
#pragma unroll
            for (int nj = 0; nj < 2; nj++) {
                mma16816(accF[mi][nj], af0, bf0[nj * 2], bf0[nj * 2 + 1]);
                mma16816(accF[mi][nj], af1, bf1[nj * 2], bf1[nj * 2 + 1]);
                imma16832(accI[mi][nj], aqh, bql[nj * 2], bql[nj * 2 + 1]);
                imma16832(accI[mi][nj], aql, bqh[nj * 2], bqh[nj * 2 + 1]);
            }
        }
    }

    const int tq = lane >> 2, tr = lane & 3;
#pragma unroll
    for (int mi = 0; mi < 4; mi++) {
        int m0 = rowBase + wm * 64 + mi * 16 + tq;
        float sa0 = sA[m0] * (1.f / 256.f);
        float sa1 = sA[m0 + 8] * (1.f / 256.f);
#pragma unroll
        for (int nj = 0; nj < 2; nj++) {
            int n = colBase + wn * 16 + nj * 8 + tr * 2;
            float2 bb = *(const float2*)(bias + n);
            float2 sb2 = *(const float2*)(sB + n);
#pragma unroll
            for (int half = 0; half < 2; half++) {
                int m = m0 + half * 8;
                float sa = half ? sa1 : sa0;
                size_t base = (size_t)m * NN + n;
                float v0 = accF[mi][nj][half*2+0] + (float)accI[mi][nj][half*2+0] * (sa * sb2.x) + bb.x;
                float v1 = accF[mi][nj][half*2+1] + (float)accI[mi][nj][half*2+1] * (sa * sb2.y) + bb.y;
                if (act == 1) { v0 = v0 * normcdff(v0); v1 = v1 * normcdff(v1); }
                if (r1) { float2 q = *(const float2*)(r1 + base); v0 += q.x; v1 += q.y; }
                if (r2) { float2 q = *(const float2*)(r2 + base); v0 += q.x; v1 += q.y; }
                if (C) { float2 ov = {v0, v1}; *(float2*)(C + base) = ov; }
                if (Ch) {
                    bf16 h0 = __float2bfloat16(v0);
                    bf16 h1 = __float2bfloat16(v1);
                    *(__nv_bfloat162*)(Ch + base) = __nv_bfloat162(h0, h1);
                    *(__nv_bfloat162*)(Cl + base) = __nv_bfloat162(
                        __float2bfloat16(v0 - __bfloat162float(h0)),
                        __float2bfloat16(v1 - __bfloat162float(h1)));
                }
            }
        }
    }
}

// ---------------- tensor-core attention (fp32 ctx out) -----------------------
static constexpr int QT = 32;
static constexpr int SCS2 = 520;
static constexpr int AO_Q = 0, AO_KV = 8192, AO_SC = 40960;
static constexpr int AO_AWH = 107520, AO_AWL = 140800;
static constexpr int ATTN_SMEM = 174080;

__device__ __forceinline__ void tile64_cpa(const bf16* __restrict__ g,
                                           int row0, int stride, uint32_t sdst, int tid) {
#pragma unroll
    for (int i = 0; i < 2; i++) {
        int idx = i * 256 + tid;
        int r = idx >> 3, c = idx & 7;
        CPA(sdst + swz(r * 128 + c * 16), g + (size_t)(row0 + r) * stride + c * 8);
    }
}

__global__ __launch_bounds__(256, 1) void attn_mma_kernel(
    const bf16* __restrict__ qkvh, const bf16* __restrict__ qkvl,
    const float* __restrict__ bias, float* __restrict__ Ctx) {
    extern __shared__ char smem[];
    const uint32_t sb = smem_u32(smem);
    const int tid = threadIdx.x;
    const int wid = tid >> 5, lane = tid & 31;
    const int wm = wid >> 2, wn = wid & 3;
    const int q0 = blockIdx.x * QT, h = blockIdx.y, b = blockIdx.z;
    const size_t base3 = (size_t)(b * S_) * D3 + h * DH_;
    const bf16* Qh = qkvh + base3;          const bf16* Ql = qkvl + base3;
    const bf16* Kh = qkvh + base3 + D_;     const bf16* Kl = qkvl + base3 + D_;
    const bf16* Vh = qkvh + base3 + 2*D_;   const bf16* Vl = qkvl + base3 + 2*D_;
    const int tq = lane >> 2, tr = lane & 3;

    {
        int r = tid >> 3, c = tid & 7;
        CPA(sb + AO_Q + swz(r * 128 + c * 16),        Qh + (size_t)(q0 + r) * D3 + c * 8);
        CPA(sb + AO_Q + 4096 + swz(r * 128 + c * 16), Ql + (size_t)(q0 + r) * D3 + c * 8);
    }
    tile64_cpa(Kh, 0, D3, sb + AO_KV, tid);
    tile64_cpa(Kl, 0, D3, sb + AO_KV + 8192, tid);
    CPA_COMMIT();
    CPA_WAIT0();
    __syncthreads();

    uint32_t qfh[4][4], qfl[4][4];
    {
        uint32_t arow = (uint32_t)((wm * 16 + (lane & 15)) * 128);
        uint32_t acol = (uint32_t)((lane >> 4) * 16);
#pragma unroll
        for (int ks = 0; ks < 4; ks++) {
            ldsm4(qfh[ks], sb + AO_Q + smx(arow, ks * 32 + acol));
            ldsm4(qfl[ks], sb + AO_Q + 4096 + smx(arow, ks * 32 + acol));
        }
    }

    const uint32_t b_row = (uint32_t)((wn * 16 + (lane & 7) + ((lane >> 4) << 3)) * 128);
    const uint32_t b_col = (uint32_t)(((lane >> 3) & 1) * 16);
    for (int c = 0; c < 8; c++) {
        if (c < 7) {
            uint32_t st = sb + AO_KV + ((c + 1) & 1) * 16384;
            tile64_cpa(Kh, (c + 1) * 64, D3, st, tid);
            tile64_cpa(Kl, (c + 1) * 64, D3, st + 8192, tid);
            CPA_COMMIT();
            CPA_WAIT1();
        } else {
            CPA_WAIT0();
        }
        __syncthreads();
        uint32_t st = sb + AO_KV + (c & 1) * 16384;

        float acc[2][4] = {};
#pragma unroll
        for (int ks = 0; ks < 4; ks++) {
            uint32_t cb = ks * 32 + b_col;
            uint32_t kh4[4], kl4[4];
            ldsm4(kh4, st + smx(b_row, cb));
            ldsm4(kl4, st + 8192 + smx(b_row, cb));
#pragma unroll
            for (int nj = 0; nj < 2; nj++) {
                mma16816(acc[nj], qfh[ks], kh4[nj * 2], kh4[nj * 2 + 1]);
                mma16816(acc[nj], qfh[ks], kl4[nj * 2], kl4[nj * 2 + 1]);
                mma16816(acc[nj], qfl[ks], kh4[nj * 2], kh4[nj * 2 + 1]);
            }
        }
        float* sc = (float*)(smem + AO_SC);
#pragma unroll
        for (int nj = 0; nj < 2; nj++) {
            int kg = c * 64 + wn * 16 + nj * 8 + tr * 2;
#pragma unroll
            for (int half = 0; half < 2; half++) {
                int m = wm * 16 + tq + half * 8;
                int rel = (q0 + m) - kg + (P_ - 1);
                sc[m * SCS2 + kg]     = acc[nj][half*2+0] * 0.125f + __ldg(&bias[rel * H_ + h]);
                sc[m * SCS2 + kg + 1] = acc[nj][half*2+1] * 0.125f + __ldg(&bias[(rel - 1) * H_ + h]);
            }
        }
        __syncthreads();
    }

    tile64_cpa(Vh, 0, D3, sb + AO_KV, tid);
    tile64_cpa(Vl, 0, D3, sb + AO_KV + 8192, tid);
    CPA_COMMIT();

    {
        float* sc = (float*)(smem + AO_SC);
        bf16* awh = (bf16*)(smem + AO_AWH);
        bf16* awl = (bf16*)(smem + AO_AWL);
#pragma unroll
        for (int rr = 0; rr < 4; rr++) {
            int r = wid * 4 + rr;
            float* row = sc + r * SCS2;
            float mx = -1e30f;
            for (int cc = lane; cc < S_; cc += 32) mx = fmaxf(mx, row[cc]);
#pragma unroll
            for (int o = 16; o > 0; o >>= 1) mx = fmaxf(mx, __shfl_xor_sync(0xffffffffu, mx, o));
            float sum = 0.f;
            for (int cc = lane; cc < S_; cc += 32) {
                float e = expf(row[cc] - mx);
                row[cc] = e;
                sum += e;
            }
#pragma unroll
            for (int o = 16; o > 0; o >>= 1) sum += __shfl_xor_sync(0xffffffffu, sum, o);
            float inv = 1.0f / sum;
            for (int cc = lane; cc < S_; cc += 32) {
                float a = row[cc] * inv;
                bf16 hi = __float2bfloat16(a);
                awh[r * SCS2 + cc] = hi;
                awl[r * SCS2 + cc] = __float2bfloat16(a - __bfloat162float(hi));
            }
        }
    }
    __syncthreads();

    float cacc[2][4] = {};
    const uint32_t aw_row = (uint32_t)((wm * 16 + (lane & 15)) * (SCS2 * 2));
    const uint32_t v_row = (uint32_t)(((lane & 7) + ((lane >> 3) & 1) * 8) * 128);
    const uint32_t v_col = (uint32_t)(wn * 32 + (lane >> 4) * 16);
    for (int c = 0; c < 8; c++) {
        if (c < 7) {
            uint32_t st = sb + AO_KV + ((c + 1) & 1) * 16384;
            tile64_cpa(Vh, (c + 1) * 64, D3, st, tid);
            tile64_cpa(Vl, (c + 1) * 64, D3, st + 8192, tid);
            CPA_COMMIT();
            CPA_WAIT1();
        } else {
            CPA_WAIT0();
        }
        __syncthreads();
        uint32_t st = sb + AO_KV + (c & 1) * 16384;

#pragma unroll
        for (int ks = 0; ks < 4; ks++) {
            uint32_t awoff = aw_row + (uint32_t)((c * 64 + ks * 16 + (lane >> 4) * 8) * 2);
            uint32_t ah4[4], al4[4];
            ldsm4(ah4, sb + AO_AWH + awoff);
            ldsm4(al4, sb + AO_AWL + awoff);
            uint32_t vro = v_row + (uint32_t)(ks * 16 * 128);
            uint32_t vh4[4], vl4[4];
            ldsm4t(vh4, st + smx(vro, v_col));
            ldsm4t(vl4, st + 8192 + smx(vro, v_col));
#pragma unroll
            for (int nj = 0; nj < 2; nj++) {
                mma16816(cacc[nj], ah4, vh4[nj * 2], vh4[nj * 2 + 1]);
                mma16816(cacc[nj], ah4, vl4[nj * 2], vl4[nj * 2 + 1]);
                mma16816(cacc[nj], al4, vh4[nj * 2], vh4[nj * 2 + 1]);
            }
        }
        __syncthreads();
    }

#pragma unroll
    for (int nj = 0; nj < 2; nj++) {
        int n = wn * 16 + nj * 8 + tr * 2;
#pragma unroll
        for (int half = 0; half < 2; half++) {
            int m = wm * 16 + tq + half * 8;
            size_t gidx = (size_t)(b * S_ + q0 + m) * D_ + h * DH_ + n;
            float2 ov = {cacc[nj][half*2+0], cacc[nj][half*2+1]};
            *(float2*)(Ctx + gidx) = ov;
        }
    }
}

// ---------------- launch ----------------------------------------------------
extern "C" void kernel_launch(void* const* d_in, const int* in_sizes, int n_in,
                              void* d_out, int out_size) {
    (void)in_sizes; (void)n_in; (void)out_size;
    const float* x    = (const float*)d_in[0];
    const float* pe   = (const float*)d_in[1];
    const float* wq   = (const float*)d_in[2];
    const float* bq   = (const float*)d_in[3];
    const float* wk   = (const float*)d_in[4];
    const float* bk   = (const float*)d_in[5];
    const float* wv   = (const float*)d_in[6];
    const float* bv   = (const float*)d_in[7];
    const float* wo   = (const float*)d_in[8];
    const float* bo   = (const float*)d_in[9];
    const float* bt   = (const float*)d_in[10];
    const float* w1   = (const float*)d_in[11];
    const float* b1   = (const float*)d_in[12];
    const float* w2   = (const float*)d_in[13];
    const float* b2   = (const float*)d_in[14];
    const float* ln1g = (const float*)d_in[15];
    const float* ln1b = (const float*)d_in[16];
    const float* ln2g = (const float*)d_in[17];
    const float* ln2b = (const float*)d_in[18];
    float* out = (float*)d_out;

    float *hb, *o1, *ctx32, *f132, *bqkv, *wt32;
    cudaGetSymbolAddress((void**)&hb, g_h);
    cudaGetSymbolAddress((void**)&o1, g_out1);
    cudaGetSymbolAddress((void**)&ctx32, g_ctx32);
    cudaGetSymbolAddress((void**)&f132, g_f132);
    cudaGetSymbolAddress((void**)&bqkv, g_bqkv);
    cudaGetSymbolAddress((void**)&wt32, g_wt32);
    bf16 *xnh, *qkvh, *qkvl, *cxh, *f1h;
    int8_t *xnhq, *xnlq, *cxhq, *cxlq, *f1hq, *f1lq;
    float *xns, *cxs, *f1s;
    cudaGetSymbolAddress((void**)&xnh, g_xn_h);   cudaGetSymbolAddress((void**)&xnhq, g_xn_hq);
    cudaGetSymbolAddress((void**)&xnlq, g_xn_lq); cudaGetSymbolAddress((void**)&xns, g_xn_s);
    cudaGetSymbolAddress((void**)&cxh, g_cx_h);   cudaGetSymbolAddress((void**)&cxhq, g_cx_hq);
    cudaGetSymbolAddress((void**)&cxlq, g_cx_lq); cudaGetSymbolAddress((void**)&cxs, g_cx_s);
    cudaGetSymbolAddress((void**)&f1h, g_f1_h);   cudaGetSymbolAddress((void**)&f1hq, g_f1_hq);
    cudaGetSymbolAddress((void**)&f1lq, g_f1_lq); cudaGetSymbolAddress((void**)&f1s, g_f1_s);
    cudaGetSymbolAddress((void**)&qkvh, g_qkv_h); cudaGetSymbolAddress((void**)&qkvl, g_qkv_l);
    bf16 *wqkvb, *wob, *w1b, *w2b;
    int8_t *wqkvhq, *wqkvlq, *wohq, *wolq, *w1hq, *w1lq, *w2hq, *w2lq;
    float *wqkvs, *wos, *w1s, *w2s;
    cudaGetSymbolAddress((void**)&wqkvb, g_wqkv_bf); cudaGetSymbolAddress((void**)&wqkvhq, g_wqkv_hq);
    cudaGetSymbolAddress((void**)&wqkvlq, g_wqkv_lq); cudaGetSymbolAddress((void**)&wqkvs, g_wqkv_s);
    cudaGetSymbolAddress((void**)&wob, g_wo_bf); cudaGetSymbolAddress((void**)&wohq, g_wo_hq);
    cudaGetSymbolAddress((void**)&wolq, g_wo_lq); cudaGetSymbolAddress((void**)&wos, g_wo_s);
    cudaGetSymbolAddress((void**)&w1b, g_w1_bf); cudaGetSymbolAddress((void**)&w1hq, g_w1_hq);
    cudaGetSymbolAddress((void**)&w1lq, g_w1_lq); cudaGetSymbolAddress((void**)&w1s, g_w1_s);
    cudaGetSymbolAddress((void**)&w2b, g_w2_bf); cudaGetSymbolAddress((void**)&w2hq, g_w2_hq);
    cudaGetSymbolAddress((void**)&w2lq, g_w2_lq); cudaGetSymbolAddress((void**)&w2s, g_w2_s);

    cudaFuncSetAttribute(attn_mma_kernel, cudaFuncAttributeMaxDynamicSharedMemorySize, ATTN_SMEM);
    cudaFuncSetAttribute(gemm_mma_kernel, cudaFuncAttributeMaxDynamicSharedMemorySize, GEMM_SMEM);

    addpe_kernel<<<(M_ * D_) / 256, 256>>>(x, pe, hb);
    packb_kernel<<<dim3(D_ / 256, L_), 256>>>(bq, bk, bv, bqkv);
    // weight prep: transpose fp32 -> row quantize
    wtransf32_kernel<<<dim3(32, 32, L_), 256>>>(wq, wt32, D_, D_, (size_t)D3 * D_, 0);
    wtransf32_kernel<<<dim3(32, 32, L_), 256>>>(wk, wt32, D_, D_, (size_t)D3 * D_, D_);
    wtransf32_kernel<<<dim3(32, 32, L_), 256>>>(wv, wt32, D_, D_, (size_t)D3 * D_, 2 * D_);
    rowquant_kernel<<<L_ * D3, 256>>>(wt32, wqkvb, wqkvhq, wqkvlq, wqkvs, D_);
    wtransf32_kernel<<<dim3(32, 32, L_), 256>>>(wo, wt32, D_, D_, (size_t)D_ * D_, 0);
    rowquant_kernel<<<L_ * D_, 256>>>(wt32, wob, wohq, wolq, wos, D_);
    wtransf32_kernel<<<dim3(F_ / 32, 32, L_), 256>>>(w1, wt32, D_, F_, (size_t)F_ * D_, 0);
    rowquant_kernel<<<L_ * F_, 256>>>(wt32, w1b, w1hq, w1lq, w1s, D_);
    wtransf32_kernel<<<dim3(32, F_ / 32, L_), 256>>>(w2, wt32, F_, D_, (size_t)D_ * F_, 0);
    rowquant_kernel<<<L_ * D_, 256>>>(wt32, w2b, w2hq, w2lq, w2s, F_);

    dim3 gQKV(D3 / 128, M_ / 128);
    dim3 gD(D_ / 128, M_ / 128);
    dim3 gF(F_ / 128, M_ / 128);
    dim3 gAttn(S_ / QT, H_, B_);

    for (int l = 0; l < L_; l++) {
        size_t oQKV = (size_t)l * D3 * D_;
        size_t oDD  = (size_t)l * D_ * D_;
        size_t oDF  = (size_t)l * D_ * F_;
        size_t oD   = (size_t)l * D_;
        size_t oF   = (size_t)l * F_;

        ln_kernel<<<M_, 256>>>(hb, ln1g + oD, ln1b + oD, xnh, xnhq, xnlq, xns);
        gemm_mma_kernel<<<gQKV, 512, GEMM_SMEM>>>(xnh, xnhq, xnlq, xns,
            wqkvb + oQKV, wqkvhq + oQKV, wqkvlq + oQKV, wqkvs + (size_t)l * D3,
            bqkv + (size_t)l * D3, nullptr, nullptr, nullptr, qkvh, qkvl, D3, D_, 0);

        attn_mma_kernel<<<gAttn, 256, ATTN_SMEM>>>(qkvh, qkvl,
            bt + (size_t)l * (2 * P_ - 1) * H_, ctx32);
        rowquant_kernel<<<M_, 256>>>(ctx32, cxh, cxhq, cxlq, cxs, D_);

        gemm_mma_kernel<<<gD, 512, GEMM_SMEM>>>(cxh, cxhq, cxlq, cxs,
            wob + oDD, wohq + oDD, wolq + oDD, wos + oD,
            bo + oD, hb, nullptr, o1, nullptr, nullptr, D_, D_, 0);

        ln_kernel<<<M_, 256>>>(o1, ln2g + oD, ln2b + oD, xnh, xnhq, xnlq, xns);
        gemm_mma_kernel<<<gF, 512, GEMM_SMEM>>>(xnh, xnhq, xnlq, xns,
            w1b + oDF, w1hq + oDF, w1lq + oDF, w1s + oF,
            b1 + oF, nullptr, nullptr, f132, nullptr, nullptr, F_, D_, 1);
        rowquant_kernel<<<M_, 256>>>(f132, f1h, f1hq, f1lq, f1s, F_);

        float* dst = (l == L_ - 1) ? out : hb;
        gemm_mma_kernel<<<gD, 512, GEMM_SMEM>>>(f1h, f1hq, f1lq, f1s,
            w2b + oDF, w2hq + oDF, w2lq + oDF, w2s + oD,
            b2 + oD, o1, hb, dst, nullptr, nullptr, D_, F_, 0);
    }
}

// round 10
// speedup vs baseline: 2.2984x; 2.2984x over previous
#include <cuda_runtime.h>
#include <cuda_bf16.h>
#include <math.h>
#include <cstdint>

using bf16 = __nv_bfloat16;

static constexpr int L_ = 6, D_ = 1024, H_ = 16, F_ = 4096, S_ = 512, B_ = 16, P_ = 512;
static constexpr int DH_ = D_ / H_;
static constexpr int M_ = B_ * S_;
static constexpr int D3 = 3 * D_;

// ---------------- scratch ----------------------------------------------------
__device__ __align__(16) float g_h[(size_t)M_ * D_];
__device__ __align__(16) float g_out1[(size_t)M_ * D_];

__device__ __align__(16) bf16 g_xn_h[(size_t)M_ * D_];
__device__ __align__(16) bf16 g_xn_l[(size_t)M_ * D_];
__device__ __align__(16) bf16 g_qkv_h[(size_t)M_ * D3];
__device__ __align__(16) bf16 g_qkv_l[(size_t)M_ * D3];
__device__ __align__(16) bf16 g_ctx_h[(size_t)M_ * D_];
__device__ __align__(16) bf16 g_ctx_l[(size_t)M_ * D_];
__device__ __align__(16) bf16 g_f1_h[(size_t)M_ * F_];
__device__ __align__(16) bf16 g_f1_l[(size_t)M_ * F_];

__device__ __align__(16) bf16 g_wqkvT_h[(size_t)L_ * D3 * D_];
__device__ __align__(16) bf16 g_wqkvT_l[(size_t)L_ * D3 * D_];
__device__ __align__(16) bf16 g_woT_h[(size_t)L_ * D_ * D_];
__device__ __align__(16) bf16 g_woT_l[(size_t)L_ * D_ * D_];
__device__ __align__(16) bf16 g_w1T_h[(size_t)L_ * D_ * F_];
__device__ __align__(16) bf16 g_w1T_l[(size_t)L_ * D_ * F_];
__device__ __align__(16) bf16 g_w2T_h[(size_t)L_ * F_ * D_];
__device__ __align__(16) bf16 g_w2T_l[(size_t)L_ * F_ * D_];
__device__ __align__(16) float g_bqkv[(size_t)L_ * D3];

// ---------------- PTX helpers -------------------------------------------------
__device__ __forceinline__ uint32_t smem_u32(const void* p) {
    uint32_t a;
    asm("{ .reg .u64 t; cvta.to.shared.u64 t, %1; cvt.u32.u64 %0, t; }" : "=r"(a) : "l"(p));
    return a;
}
__device__ __forceinline__ void ldsm4(uint32_t* r, uint32_t addr) {
    asm volatile("ldmatrix.sync.aligned.m8n8.x4.shared.b16 {%0,%1,%2,%3}, [%4];"
                 : "=r"(r[0]), "=r"(r[1]), "=r"(r[2]), "=r"(r[3]) : "r"(addr));
}
__device__ __forceinline__ void ldsm4t(uint32_t* r, uint32_t addr) {
    asm volatile("ldmatrix.sync.aligned.m8n8.x4.trans.shared.b16 {%0,%1,%2,%3}, [%4];"
                 : "=r"(r[0]), "=r"(r[1]), "=r"(r[2]), "=r"(r[3]) : "r"(addr));
}
__device__ __forceinline__ void mma16816(float* d, const uint32_t* a, uint32_t b0, uint32_t b1) {
    asm volatile("mma.sync.aligned.m16n8k16.row.col.f32.bf16.bf16.f32 "
                 "{%0,%1,%2,%3}, {%4,%5,%6,%7}, {%8,%9}, {%0,%1,%2,%3};"
                 : "+f"(d[0]), "+f"(d[1]), "+f"(d[2]), "+f"(d[3])
                 : "r"(a[0]), "r"(a[1]), "r"(a[2]), "r"(a[3]), "r"(b0), "r"(b1));
}
#define CPA(dst, src)  asm volatile("cp.async.cg.shared.global [%0], [%1], 16;" :: "r"(dst), "l"(src))
#define CPA_COMMIT()   asm volatile("cp.async.commit_group;" ::: "memory")
#define CPA_WAIT1()    asm volatile("cp.async.wait_group 1;" ::: "memory")
#define CPA_WAIT0()    asm volatile("cp.async.wait_group 0;" ::: "memory")

__device__ __forceinline__ uint32_t swz(uint32_t off)   { return off ^ ((off >> 3) & 0x70); }
__device__ __forceinline__ uint32_t swz64(uint32_t off) { return off ^ ((off >> 3) & 0x30); }
__device__ __forceinline__ uint32_t smx(uint32_t r, uint32_t c)   { return r + (c ^ ((r >> 3) & 0x70)); }
__device__ __forceinline__ uint32_t smx64(uint32_t r, uint32_t c) { return r + (c ^ ((r >> 3) & 0x30)); }

// ---------------- h = x + pe -------------------------------------------------
__global__ __launch_bounds__(256) void addpe_kernel(const float* __restrict__ x,
                                                    const float* __restrict__ pe,
                                                    float* __restrict__ h) {
    int i = blockIdx.x * 256 + threadIdx.x;
    h[i] = x[i] + pe[i & (S_ * D_ - 1)];
}

// ---------------- pack qkv bias ----------------------------------------------
__global__ __launch_bounds__(256) void packb_kernel(const float* __restrict__ bq,
                                                    const float* __restrict__ bk,
                                                    const float* __restrict__ bv,
                                                    float* __restrict__ o) {
    int l = blockIdx.y;
    int i = blockIdx.x * 256 + threadIdx.x;
    o[(size_t)l * D3 + i]          = bq[l * D_ + i];
    o[(size_t)l * D3 + D_ + i]     = bk[l * D_ + i];
    o[(size_t)l * D3 + 2 * D_ + i] = bv[l * D_ + i];
}

// ---------------- weight transpose + bf16 split: W[K,N] -> T[N,K] hi/lo -----
__global__ __launch_bounds__(256) void wtrans_kernel(const float* __restrict__ W,
                                                     bf16* __restrict__ Th,
                                                     bf16* __restrict__ Tl,
                                                     int K, int N, size_t out_ls) {
    __shared__ float t[32][33];
    size_t inoff  = (size_t)blockIdx.z * K * N;
    size_t outoff = (size_t)blockIdx.z * out_ls;
    int k0 = blockIdx.y * 32, n0 = blockIdx.x * 32;
    int tx = threadIdx.x & 31, ty = threadIdx.x >> 5;
#pragma unroll
    for (int i = 0; i < 32; i += 8)
        t[ty + i][tx] = W[inoff + (size_t)(k0 + ty + i) * N + n0 + tx];
    __syncthreads();
#pragma unroll
    for (int i = 0; i < 32; i += 8) {
        float v = t[tx][ty + i];
        bf16 hi = __float2bfloat16(v);
        size_t idx = outoff + (size_t)(n0 + ty + i) * K + k0 + tx;
        Th[idx] = hi;
        Tl[idx] = __float2bfloat16(v - __bfloat162float(hi));
    }
}

// merged q/k/v transpose: z = l*3 + which; output rows offset which*D in [D3,K]
__global__ __launch_bounds__(256) void wtransqkv_kernel(const float* __restrict__ wq,
                                                        const float* __restrict__ wk,
                                                        const float* __restrict__ wv,
                                                        bf16* __restrict__ Th,
                                                        bf16* __restrict__ Tl) {
    __shared__ float t[32][33];
    int z = blockIdx.z;
    int l = z / 3, which = z - l * 3;
    const float* W = (which == 0) ? wq : (which == 1) ? wk : wv;
    size_t inoff  = (size_t)l * D_ * D_;
    size_t outoff = (size_t)l * D3 * D_ + (size_t)which * D_ * D_;
    int k0 = blockIdx.y * 32, n0 = blockIdx.x * 32;
    int tx = threadIdx.x & 31, ty = threadIdx.x >> 5;
#pragma unroll
    for (int i = 0; i < 32; i += 8)
        t[ty + i][tx] = W[inoff + (size_t)(k0 + ty + i) * D_ + n0 + tx];
    __syncthreads();
#pragma unroll
    for (int i = 0; i < 32; i += 8) {
        float v = t[tx][ty + i];
        bf16 hi = __float2bfloat16(v);
        size_t idx = outoff + (size_t)(n0 + ty + i) * D_ + k0 + tx;
        Th[idx] = hi;
        Tl[idx] = __float2bfloat16(v - __bfloat162float(hi));
    }
}

// ---------------- LayerNorm: fp32 in -> bf16 hi/lo out -----------------------
__global__ __launch_bounds__(256) void ln_kernel(const float* __restrict__ x,
                                                 const float* __restrict__ g,
                                                 const float* __restrict__ b,
                                                 bf16* __restrict__ yh,
                                                 bf16* __restrict__ yl) {
    int row = blockIdx.x, tid = threadIdx.x;
    float4 f = *(const float4*)(x + (size_t)row * D_ + tid * 4);
    float s  = f.x + f.y + f.z + f.w;
    float ss = f.x*f.x + f.y*f.y + f.z*f.z + f.w*f.w;
#pragma unroll
    for (int o = 16; o > 0; o >>= 1) {
        s  += __shfl_xor_sync(0xffffffffu, s, o);
        ss += __shfl_xor_sync(0xffffffffu, ss, o);
    }
    __shared__ float rs[8], rss[8];
    if ((tid & 31) == 0) { rs[tid >> 5] = s; rss[tid >> 5] = ss; }
    __syncthreads();
    float ts = 0.f, tss = 0.f;
#pragma unroll
    for (int i = 0; i < 8; i++) { ts += rs[i]; tss += rss[i]; }
    float mean = ts * (1.0f / D_);
    float var  = tss * (1.0f / D_) - mean * mean;
    float r    = rsqrtf(var + 1e-6f);
    float4 g4 = *(const float4*)(g + tid * 4);
    float4 b4 = *(const float4*)(b + tid * 4);
    float o[4];
    o[0]=(f.x-mean)*r*g4.x+b4.x; o[1]=(f.y-mean)*r*g4.y+b4.y;
    o[2]=(f.z-mean)*r*g4.z+b4.z; o[3]=(f.w-mean)*r*g4.w+b4.w;
    size_t base = (size_t)row * D_ + tid * 4;
#pragma unroll
    for (int j = 0; j < 4; j += 2) {
        bf16 h0 = __float2bfloat16(o[j]);
        bf16 h1 = __float2bfloat16(o[j + 1]);
        *(__nv_bfloat162*)(yh + base + j) = __nv_bfloat162(h0, h1);
        *(__nv_bfloat162*)(yl + base + j) = __nv_bfloat162(
            __float2bfloat16(o[j] - __bfloat162float(h0)),
            __float2bfloat16(o[j + 1] - __bfloat162float(h1)));
    }
}

// ---------------- split-bf16 mma.sync GEMM 128x128, Kc=32, SW64, x3, occ2 ---
static constexpr int TILE32 = 128 * 32 * 2;
static constexpr int S_AH = 0, S_AL = TILE32, S_BH = 2 * TILE32, S_BL = 3 * TILE32;
static constexpr int STAGEB = 4 * TILE32;       // 32 KB
static constexpr int GEMM_SMEM = 3 * STAGEB;    // 96 KB -> 2 CTAs/SM

__device__ __forceinline__ void tile_cpa32(const bf16* __restrict__ g,
                                           int row0, int stride, int k0,
                                           uint32_t sdst, int tid) {
#pragma unroll
    for (int i = 0; i < 2; i++) {
        int idx = i * 256 + tid;
        int r = idx >> 2, c = idx & 3;
        CPA(sdst + swz64(r * 64 + c * 16), g + (size_t)(row0 + r) * stride + k0 + c * 8);
    }
}

__global__ __launch_bounds__(256, 2) void gemm_mma_kernel(
    const bf16* __restrict__ Ah, const bf16* __restrict__ Al,
    const bf16* __restrict__ Bh, const bf16* __restrict__ Bl,
    const float* __restrict__ bias, const float* __restrict__ r1,
    const float* __restrict__ r2, float* __restrict__ C,
    bf16* __restrict__ Ch, bf16* __restrict__ Cl,
    int NN, int KK, int act) {
    extern __shared__ char smem[];
    const uint32_t sb = smem_u32(smem);
    const int tid = threadIdx.x;
    const int wid = tid >> 5, lane = tid & 31;
    const int wm = wid >> 2, wn = wid & 3;
    const int rowBase = blockIdx.y * 128, colBase = blockIdx.x * 128;

    float acc[4][4][4];
#pragma unroll
    for (int i = 0; i < 4; i++)
#pragma unroll
        for (int j = 0; j < 4; j++)
#pragma unroll
            for (int q = 0; q < 4; q++) acc[i][j][q] = 0.f;

    const uint32_t a_row = (uint32_t)((wm * 64 + (lane & 15)) * 64);
    const uint32_t a_col = (uint32_t)((lane >> 4) * 16);
    const uint32_t b_row0 = (uint32_t)((wn * 32 + (lane & 7) + ((lane >> 4) << 3)) * 64);
    const uint32_t b_col = (uint32_t)(((lane >> 3) & 1) * 16);

    const int nc = KK / 32;
    tile_cpa32(Ah, rowBase, KK, 0, sb + S_AH, tid);
    tile_cpa32(Al, rowBase, KK, 0, sb + S_AL, tid);
    tile_cpa32(Bh, colBase, KK, 0, sb + S_BH, tid);
    tile_cpa32(Bl, colBase, KK, 0, sb + S_BL, tid);
    CPA_COMMIT();
    {
        uint32_t st = sb + STAGEB;
        tile_cpa32(Ah, rowBase, KK, 32, st + S_AH, tid);
        tile_cpa32(Al, rowBase, KK, 32, st + S_AL, tid);
        tile_cpa32(Bh, colBase, KK, 32, st + S_BH, tid);
        tile_cpa32(Bl, colBase, KK, 32, st + S_BL, tid);
    }
    CPA_COMMIT();

    for (int c = 0; c < nc; c++) {
        if (c + 1 < nc) CPA_WAIT1(); else CPA_WAIT0();
        __syncthreads();
        if (c + 2 < nc) {
            uint32_t st = sb + ((c + 2) % 3) * STAGEB;
            int k0 = (c + 2) * 32;
            tile_cpa32(Ah, rowBase, KK, k0, st + S_AH, tid);
            tile_cpa32(Al, rowBase, KK, k0, st + S_AL, tid);
            tile_cpa32(Bh, colBase, KK, k0, st + S_BH, tid);
            tile_cpa32(Bl, colBase, KK, k0, st + S_BL, tid);
            CPA_COMMIT();
        }
        uint32_t st = sb + (c % 3) * STAGEB;

#pragma unroll
        for (int ks = 0; ks < 2; ks++) {
            const uint32_t kb = ks * 32;
            uint32_t bh[2][4], bl[2][4];
#pragma unroll
            for (int g = 0; g < 2; g++) {
                uint32_t roff = b_row0 + (uint32_t)(g * 16 * 64);
                ldsm4(bh[g], st + S_BH + smx64(roff, kb + b_col));
                ldsm4(bl[g], st + S_BL + smx64(roff, kb + b_col));
            }
#pragma unroll
            for (int mi = 0; mi < 4; mi++) {
                uint32_t roff = a_row + (uint32_t)(mi * 16 * 64);
                uint32_t a_h[4], a_l[4];
                ldsm4(a_h, st + S_AH + smx64(roff, kb + a_col));
                ldsm4(a_l, st + S_AL + smx64(roff, kb + a_col));
#pragma unroll
                for (int nj = 0; nj < 4; nj++) {
                    int g = nj >> 1, o = (nj & 1) * 2;
                    uint32_t h0 = bh[g][o], h1 = bh[g][o + 1];
                    uint32_t l0 = bl[g][o], l1 = bl[g][o + 1];
                    mma16816(acc[mi][nj], a_h, h0, h1);
                    mma16816(acc[mi][nj], a_h, l0, l1);
                    mma16816(acc[mi][nj], a_l, h0, h1);
                }
            }
        }
    }

    const int tq = lane >> 2, tr = lane & 3;
#pragma unroll
    for (int mi = 0; mi < 4; mi++) {
#pragma unroll
        for (int nj = 0; nj < 4; nj++) {
            int n = colBase + wn * 32 + nj * 8 + tr * 2;
            float2 bb = *(const float2*)(bias + n);
#pragma unroll
            for (int half = 0; half < 2; half++) {
                int m = rowBase + wm * 64 + mi * 16 + tq + half * 8;
                size_t base = (size_t)m * NN + n;
                float v0 = acc[mi][nj][half * 2 + 0] + bb.x;
                float v1 = acc[mi][nj][half * 2 + 1] + bb.y;
                if (act == 1) { v0 = v0 * normcdff(v0); v1 = v1 * normcdff(v1); }
                if (r1) { float2 q = *(const float2*)(r1 + base); v0 += q.x; v1 += q.y; }
                if (r2) { float2 q = *(const float2*)(r2 + base); v0 += q.x; v1 += q.y; }
                if (C) { float2 ov = {v0, v1}; *(float2*)(C + base) = ov; }
                if (Ch) {
                    bf16 h0 = __float2bfloat16(v0);
                    bf16 h1 = __float2bfloat16(v1);
                    *(__nv_bfloat162*)(Ch + base) = __nv_bfloat162(h0, h1);
                    *(__nv_bfloat162*)(Cl + base) = __nv_bfloat162(
                        __float2bfloat16(v0 - __bfloat162float(h0)),
                        __float2bfloat16(v1 - __bfloat162float(h1)));
                }
            }
        }
    }
}

// ---------------- tensor-core attention --------------------------------------
static constexpr int QT = 32;
static constexpr int SCS2 = 520;
static constexpr int AO_Q = 0, AO_KV = 8192, AO_SC = 40960;
static constexpr int AO_AWH = 107520, AO_AWL = 140800;
static constexpr int ATTN_SMEM = 174080;

__device__ __forceinline__ void tile64_cpa(const bf16* __restrict__ g,
                                           int row0, int stride, uint32_t sdst, int tid) {
#pragma unroll
    for (int i = 0; i < 2; i++) {
        int idx = i * 256 + tid;
        int r = idx >> 3, c = idx & 7;
        CPA(sdst + swz(r * 128 + c * 16), g + (size_t)(row0 + r) * stride + c * 8);
    }
}

__global__ __launch_bounds__(256, 1) void attn_mma_kernel(
    const bf16* __restrict__ qkvh, const bf16* __restrict__ qkvl,
    const float* __restrict__ bias,
    bf16* __restrict__ Ch, bf16* __restrict__ Cl) {
    extern __shared__ char smem[];
    const uint32_t sb = smem_u32(smem);
    const int tid = threadIdx.x;
    const int wid = tid >> 5, lane = tid & 31;
    const int wm = wid >> 2, wn = wid & 3;
    const int q0 = blockIdx.x * QT, h = blockIdx.y, b = blockIdx.z;
    const size_t base3 = (size_t)(b * S_) * D3 + h * DH_;
    const bf16* Qh = qkvh + base3;          const bf16* Ql = qkvl + base3;
    const bf16* Kh = qkvh + base3 + D_;     const bf16* Kl = qkvl + base3 + D_;
    const bf16* Vh = qkvh + base3 + 2*D_;   const bf16* Vl = qkvl + base3 + 2*D_;
    const int tq = lane >> 2, tr = lane & 3;

    {
        int r = tid >> 3, c = tid & 7;
        CPA(sb + AO_Q + swz(r * 128 + c * 16),        Qh + (size_t)(q0 + r) * D3 + c * 8);
        CPA(sb + AO_Q + 4096 + swz(r * 128 + c * 16), Ql + (size_t)(q0 + r) * D3 + c * 8);
    }
    tile64_cpa(Kh, 0, D3, sb + AO_KV, tid);
    tile64_cpa(Kl, 0, D3, sb + AO_KV + 8192, tid);
    CPA_COMMIT();
    CPA_WAIT0();
    __syncthreads();

    uint32_t qfh[4][4], qfl[4][4];
    {
        uint32_t arow = (uint32_t)((wm * 16 + (lane & 15)) * 128);
        uint32_t acol = (uint32_t)((lane >> 4) * 16);
#pragma unroll
        for (int ks = 0; ks < 4; ks++) {
            ldsm4(qfh[ks], sb + AO_Q + smx(arow, ks * 32 + acol));
            ldsm4(qfl[ks], sb + AO_Q + 4096 + smx(arow, ks * 32 + acol));
        }
    }

    const uint32_t b_row = (uint32_t)((wn * 16 + (lane & 7) + ((lane >> 4) << 3)) * 128);
    const uint32_t b_col = (uint32_t)(((lane >> 3) & 1) * 16);
    for (int c = 0; c < 8; c++) {
        if (c < 7) {
            uint32_t st = sb + AO_KV + ((c + 1) & 1) * 16384;
            tile64_cpa(Kh, (c + 1) * 64, D3, st, tid);
            tile64_cpa(Kl, (c + 1) * 64, D3, st + 8192, tid);
            CPA_COMMIT();
            CPA_WAIT1();
        } else {
            CPA_WAIT0();
        }
        __syncthreads();
        uint32_t st = sb + AO_KV + (c & 1) * 16384;

        float acc[2][4] = {};
#pragma unroll
        for (int ks = 0; ks < 4; ks++) {
            uint32_t cb = ks * 32 + b_col;
            uint32_t kh4[4], kl4[4];
            ldsm4(kh4, st + smx(b_row, cb));
            ldsm4(kl4, st + 8192 + smx(b_row, cb));
#pragma unroll
            for (int nj = 0; nj < 2; nj++) {
                mma16816(acc[nj], qfh[ks], kh4[nj * 2], kh4[nj * 2 + 1]);
                mma16816(acc[nj], qfh[ks], kl4[nj * 2], kl4[nj * 2 + 1]);
                mma16816(acc[nj], qfl[ks], kh4[nj * 2], kh4[nj * 2 + 1]);
            }
        }
        float* sc = (float*)(smem + AO_SC);
#pragma unroll
        for (int nj = 0; nj < 2; nj++) {
            int kg = c * 64 + wn * 16 + nj * 8 + tr * 2;
#pragma unroll
            for (int half = 0; half < 2; half++) {
                int m = wm * 16 + tq + half * 8;
                int rel = (q0 + m) - kg + (P_ - 1);
                sc[m * SCS2 + kg]     = acc[nj][half*2+0] * 0.125f + __ldg(&bias[rel * H_ + h]);
                sc[m * SCS2 + kg + 1] = acc[nj][half*2+1] * 0.125f + __ldg(&bias[(rel - 1) * H_ + h]);
            }
        }
        __syncthreads();
    }

    tile64_cpa(Vh, 0, D3, sb + AO_KV, tid);
    tile64_cpa(Vl, 0, D3, sb + AO_KV + 8192, tid);
    CPA_COMMIT();

    {
        float* sc = (float*)(smem + AO_SC);
        bf16* awh = (bf16*)(smem + AO_AWH);
        bf16* awl = (bf16*)(smem + AO_AWL);
#pragma unroll
        for (int rr = 0; rr < 4; rr++) {
            int r = wid * 4 + rr;
            float* row = sc + r * SCS2;
            float mx = -1e30f;
            for (int cc = lane; cc < S_; cc += 32) mx = fmaxf(mx, row[cc]);
#pragma unroll
            for (int o = 16; o > 0; o >>= 1) mx = fmaxf(mx, __shfl_xor_sync(0xffffffffu, mx, o));
            float sum = 0.f;
            for (int cc = lane; cc < S_; cc += 32) {
                float e = expf(row[cc] - mx);
                row[cc] = e;
                sum += e;
            }
#pragma unroll
            for (int o = 16; o > 0; o >>= 1) sum += __shfl_xor_sync(0xffffffffu, sum, o);
            float inv = 1.0f / sum;
            for (int cc = lane; cc < S_; cc += 32) {
                float a = row[cc] * inv;
                bf16 hi = __float2bfloat16(a);
                awh[r * SCS2 + cc] = hi;
                awl[r * SCS2 + cc] = __float2bfloat16(a - __bfloat162float(hi));
            }
        }
    }
    __syncthreads();

    float cacc[2][4] = {};
    const uint32_t aw_row = (uint32_t)((wm * 16 + (lane & 15)) * (SCS2 * 2));
    const uint32_t v_row = (uint32_t)(((lane & 7) + ((lane >> 3) & 1) * 8) * 128);
    const uint32_t v_col = (uint32_t)(wn * 32 + (lane >> 4) * 16);
    for (int c = 0; c < 8; c++) {
        if (c < 7) {
            uint32_t st = sb + AO_KV + ((c + 1) & 1) * 16384;
            tile64_cpa(Vh, (c + 1) * 64, D3, st, tid);
            tile64_cpa(Vl, (c + 1) * 64, D3, st + 8192, tid);
            CPA_COMMIT();
            CPA_WAIT1();
        } else {
            CPA_WAIT0();
        }
        __syncthreads();
        uint32_t st = sb + AO_KV + (c & 1) * 16384;

#pragma unroll
        for (int ks = 0; ks < 4; ks++) {
            uint32_t awoff = aw_row + (uint32_t)((c * 64 + ks * 16 + (lane >> 4) * 8) * 2);
            uint32_t ah4[4], al4[4];
            ldsm4(ah4, sb + AO_AWH + awoff);
            ldsm4(al4, sb + AO_AWL + awoff);
            uint32_t vro = v_row + (uint32_t)(ks * 16 * 128);
            uint32_t vh4[4], vl4[4];
            ldsm4t(vh4, st + smx(vro, v_col));
            ldsm4t(vl4, st + 8192 + smx(vro, v_col));
#pragma unroll
            for (int nj = 0; nj < 2; nj++) {
                mma16816(cacc[nj], ah4, vh4[nj * 2], vh4[nj * 2 + 1]);
                mma16816(cacc[nj], ah4, vl4[nj * 2], vl4[nj * 2 + 1]);
                mma16816(cacc[nj], al4, vh4[nj * 2], vh4[nj * 2 + 1]);
            }
        }
        __syncthreads();
    }

#pragma unroll
    for (int nj = 0; nj < 2; nj++) {
        int n = wn * 16 + nj * 8 + tr * 2;
#pragma unroll
        for (int half = 0; half < 2; half++) {
            int m = wm * 16 + tq + half * 8;
            size_t gidx = (size_t)(b * S_ + q0 + m) * D_ + h * DH_ + n;
            float v0 = cacc[nj][half*2+0];
            float v1 = cacc[nj][half*2+1];
            bf16 h0 = __float2bfloat16(v0);
            bf16 h1 = __float2bfloat16(v1);
            *(__nv_bfloat162*)(Ch + gidx) = __nv_bfloat162(h0, h1);
            *(__nv_bfloat162*)(Cl + gidx) = __nv_bfloat162(
                __float2bfloat16(v0 - __bfloat162float(h0)),
                __float2bfloat16(v1 - __bfloat162float(h1)));
        }
    }
}

// ---------------- launch ----------------------------------------------------
extern "C" void kernel_launch(void* const* d_in, const int* in_sizes, int n_in,
                              void* d_out, int out_size) {
    (void)in_sizes; (void)n_in; (void)out_size;
    const float* x    = (const float*)d_in[0];
    const float* pe   = (const float*)d_in[1];
    const float* wq   = (const float*)d_in[2];
    const float* bq   = (const float*)d_in[3];
    const float* wk   = (const float*)d_in[4];
    const float* bk   = (const float*)d_in[5];
    const float* wv   = (const float*)d_in[6];
    const float* bv   = (const float*)d_in[7];
    const float* wo   = (const float*)d_in[8];
    const float* bo   = (const float*)d_in[9];
    const float* bt   = (const float*)d_in[10];
    const float* w1   = (const float*)d_in[11];
    const float* b1   = (const float*)d_in[12];
    const float* w2   = (const float*)d_in[13];
    const float* b2   = (const float*)d_in[14];
    const float* ln1g = (const float*)d_in[15];
    const float* ln1b = (const float*)d_in[16];
    const float* ln2g = (const float*)d_in[17];
    const float* ln2b = (const float*)d_in[18];
    float* out = (float*)d_out;

    float *hb, *o1, *bqkv;
    bf16 *xnh, *xnl, *qkvh, *qkvl, *cxh, *cxl, *f1h, *f1l;
    bf16 *wqkvhp, *wqkvlp, *woh, *wol, *w1h, *w1l, *w2h, *w2l;
    cudaGetSymbolAddress((void**)&hb,   g_h);
    cudaGetSymbolAddress((void**)&o1,   g_out1);
    cudaGetSymbolAddress((void**)&bqkv, g_bqkv);
    cudaGetSymbolAddress((void**)&xnh,  g_xn_h);  cudaGetSymbolAddress((void**)&xnl, g_xn_l);
    cudaGetSymbolAddress((void**)&qkvh, g_qkv_h); cudaGetSymbolAddress((void**)&qkvl, g_qkv_l);
    cudaGetSymbolAddress((void**)&cxh,  g_ctx_h); cudaGetSymbolAddress((void**)&cxl, g_ctx_l);
    cudaGetSymbolAddress((void**)&f1h,  g_f1_h);  cudaGetSymbolAddress((void**)&f1l, g_f1_l);
    cudaGetSymbolAddress((void**)&wqkvhp, g_wqkvT_h); cudaGetSymbolAddress((void**)&wqkvlp, g_wqkvT_l);
    cudaGetSymbolAddress((void**)&woh,  g_woT_h); cudaGetSymbolAddress((void**)&wol, g_woT_l);
    cudaGetSymbolAddress((void**)&w1h,  g_w1T_h); cudaGetSymbolAddress((void**)&w1l, g_w1T_l);
    cudaGetSymbolAddress((void**)&w2h,  g_w2T_h); cudaGetSymbolAddress((void**)&w2l, g_w2T_l);

    cudaFuncSetAttribute(attn_mma_kernel, cudaFuncAttributeMaxDynamicSharedMemorySize, ATTN_SMEM);
    cudaFuncSetAttribute(gemm_mma_kernel, cudaFuncAttributeMaxDynamicSharedMemorySize, GEMM_SMEM);

    dim3 gQKV(D3 / 128, M_ / 128);
    dim3 gD(D_ / 128, M_ / 128);
    dim3 gF(F_ / 128, M_ / 128);
    dim3 gAttn(S_ / QT, H_, B_);

    // Launch order chosen so the FIRST gemm_mma_kernel is launch #6 (ncu -s 5 -c 1).
    addpe_kernel<<<(M_ * D_) / 256, 256>>>(x, pe, hb);                                   // 1
    packb_kernel<<<dim3(D_ / 256, L_), 256>>>(bq, bk, bv, bqkv);                         // 2
    wtransqkv_kernel<<<dim3(32, 32, 3 * L_), 256>>>(wq, wk, wv, wqkvhp, wqkvlp);         // 3
    wtrans_kernel<<<dim3(32, 32, L_), 256>>>(wo, woh, wol, D_, D_, (size_t)D_ * D_);     // 4
    ln_kernel<<<M_, 256>>>(hb, ln1g, ln1b, xnh, xnl);                                    // 5
    gemm_mma_kernel<<<gQKV, 256, GEMM_SMEM>>>(xnh, xnl, wqkvhp, wqkvlp,                  // 6 <- profiled
        bqkv, nullptr, nullptr, nullptr, qkvh, qkvl, D3, D_, 0);
    // remaining weight prep (needed before f1/f2 gemms)
    wtrans_kernel<<<dim3(F_ / 32, D_ / 32, L_), 256>>>(w1, w1h, w1l, D_, F_, (size_t)D_ * F_);
    wtrans_kernel<<<dim3(D_ / 32, F_ / 32, L_), 256>>>(w2, w2h, w2l, F_, D_, (size_t)F_ * D_);

    for (int l = 0; l < L_; l++) {
        size_t oQKV = (size_t)l * D3 * D_;
        size_t oDD  = (size_t)l * D_ * D_;
        size_t oDF  = (size_t)l * D_ * F_;
        size_t oD   = (size_t)l * D_;
        size_t oF   = (size_t)l * F_;

        if (l > 0) {
            ln_kernel<<<M_, 256>>>(hb, ln1g + oD, ln1b + oD, xnh, xnl);
            gemm_mma_kernel<<<gQKV, 256, GEMM_SMEM>>>(xnh, xnl, wqkvhp + oQKV, wqkvlp + oQKV,
                bqkv + (size_t)l * D3, nullptr, nullptr, nullptr, qkvh, qkvl, D3, D_, 0);
        }

        attn_mma_kernel<<<gAttn, 256, ATTN_SMEM>>>(qkvh, qkvl,
            bt + (size_t)l * (2 * P_ - 1) * H_, cxh, cxl);

        gemm_mma_kernel<<<gD, 256, GEMM_SMEM>>>(cxh, cxl, woh + oDD, wol + oDD,
            bo + oD, hb, nullptr, o1, nullptr, nullptr, D_, D_, 0);

        ln_kernel<<<M_, 256>>>(o1, ln2g + oD, ln2b + oD, xnh, xnl);
        gemm_mma_kernel<<<gF, 256, GEMM_SMEM>>>(xnh, xnl, w1h + oDF, w1l + oDF,
            b1 + oF, nullptr, nullptr, nullptr, f1h, f1l, F_, D_, 1);
        float* dst = (l == L_ - 1) ? out : hb;
        gemm_mma_kernel<<<gD, 256, GEMM_SMEM>>>(f1h, f1l, w2h + oDF, w2l + oDF,
            b2 + oD, o1, hb, dst, nullptr, nullptr, D_, F_, 0);
    }
}

// round 11
// speedup vs baseline: 2.2990x; 1.0003x over previous
#include <cuda_runtime.h>
#include <cuda_bf16.h>
#include <math.h>
#include <cstdint>

using bf16 = __nv_bfloat16;

static constexpr int L_ = 6, D_ = 1024, H_ = 16, F_ = 4096, S_ = 512, B_ = 16, P_ = 512;
static constexpr int DH_ = D_ / H_;
static constexpr int M_ = B_ * S_;
static constexpr int D3 = 3 * D_;

// ---------------- scratch ----------------------------------------------------
__device__ __align__(16) float g_h[(size_t)M_ * D_];
__device__ __align__(16) float g_out1[(size_t)M_ * D_];

__device__ __align__(16) bf16 g_xn_h[(size_t)M_ * D_];
__device__ __align__(16) bf16 g_xn_l[(size_t)M_ * D_];
__device__ __align__(16) bf16 g_qkv_h[(size_t)M_ * D3];
__device__ __align__(16) bf16 g_qkv_l[(size_t)M_ * D3];
__device__ __align__(16) bf16 g_ctx_h[(size_t)M_ * D_];
__device__ __align__(16) bf16 g_ctx_l[(size_t)M_ * D_];
__device__ __align__(16) bf16 g_f1_h[(size_t)M_ * F_];
__device__ __align__(16) bf16 g_f1_l[(size_t)M_ * F_];

__device__ __align__(16) bf16 g_wqkvT_h[(size_t)L_ * D3 * D_];
__device__ __align__(16) bf16 g_wqkvT_l[(size_t)L_ * D3 * D_];
__device__ __align__(16) bf16 g_woT_h[(size_t)L_ * D_ * D_];
__device__ __align__(16) bf16 g_woT_l[(size_t)L_ * D_ * D_];
__device__ __align__(16) bf16 g_w1T_h[(size_t)L_ * D_ * F_];
__device__ __align__(16) bf16 g_w1T_l[(size_t)L_ * D_ * F_];
__device__ __align__(16) bf16 g_w2T_h[(size_t)L_ * F_ * D_];
__device__ __align__(16) bf16 g_w2T_l[(size_t)L_ * F_ * D_];
__device__ __align__(16) float g_bqkv[(size_t)L_ * D3];

// ---------------- PTX helpers -------------------------------------------------
__device__ __forceinline__ uint32_t smem_u32(const void* p) {
    uint32_t a;
    asm("{ .reg .u64 t; cvta.to.shared.u64 t, %1; cvt.u32.u64 %0, t; }" : "=r"(a) : "l"(p));
    return a;
}
__device__ __forceinline__ void ldsm4(uint32_t* r, uint32_t addr) {
    asm volatile("ldmatrix.sync.aligned.m8n8.x4.shared.b16 {%0,%1,%2,%3}, [%4];"
                 : "=r"(r[0]), "=r"(r[1]), "=r"(r[2]), "=r"(r[3]) : "r"(addr));
}
__device__ __forceinline__ void ldsm4t(uint32_t* r, uint32_t addr) {
    asm volatile("ldmatrix.sync.aligned.m8n8.x4.trans.shared.b16 {%0,%1,%2,%3}, [%4];"
                 : "=r"(r[0]), "=r"(r[1]), "=r"(r[2]), "=r"(r[3]) : "r"(addr));
}
__device__ __forceinline__ void mma16816(float* d, const uint32_t* a, uint32_t b0, uint32_t b1) {
    asm volatile("mma.sync.aligned.m16n8k16.row.col.f32.bf16.bf16.f32 "
                 "{%0,%1,%2,%3}, {%4,%5,%6,%7}, {%8,%9}, {%0,%1,%2,%3};"
                 : "+f"(d[0]), "+f"(d[1]), "+f"(d[2]), "+f"(d[3])
                 : "r"(a[0]), "r"(a[1]), "r"(a[2]), "r"(a[3]), "r"(b0), "r"(b1));
}
#define CPA(dst, src)  asm volatile("cp.async.cg.shared.global [%0], [%1], 16;" :: "r"(dst), "l"(src))
#define CPA_COMMIT()   asm volatile("cp.async.commit_group;" ::: "memory")
#define CPA_WAIT1()    asm volatile("cp.async.wait_group 1;" ::: "memory")
#define CPA_WAIT0()    asm volatile("cp.async.wait_group 0;" ::: "memory")

__device__ __forceinline__ uint32_t swz(uint32_t off)   { return off ^ ((off >> 3) & 0x70); }
__device__ __forceinline__ uint32_t swz64(uint32_t off) { return off ^ ((off >> 3) & 0x30); }
__device__ __forceinline__ uint32_t smx(uint32_t r, uint32_t c)   { return r + (c ^ ((r >> 3) & 0x70)); }
__device__ __forceinline__ uint32_t smx64(uint32_t r, uint32_t c) { return r + (c ^ ((r >> 3) & 0x30)); }

// ---------------- h = x + pe -------------------------------------------------
__global__ __launch_bounds__(256) void addpe_kernel(const float* __restrict__ x,
                                                    const float* __restrict__ pe,
                                                    float* __restrict__ h) {
    int i = blockIdx.x * 256 + threadIdx.x;
    h[i] = x[i] + pe[i & (S_ * D_ - 1)];
}

// ---------------- pack qkv bias ----------------------------------------------
__global__ __launch_bounds__(256) void packb_kernel(const float* __restrict__ bq,
                                                    const float* __restrict__ bk,
                                                    const float* __restrict__ bv,
                                                    float* __restrict__ o) {
    int l = blockIdx.y;
    int i = blockIdx.x * 256 + threadIdx.x;
    o[(size_t)l * D3 + i]          = bq[l * D_ + i];
    o[(size_t)l * D3 + D_ + i]     = bk[l * D_ + i];
    o[(size_t)l * D3 + 2 * D_ + i] = bv[l * D_ + i];
}

// ---------------- weight transpose + bf16 split: W[K,N] -> T[N,K] hi/lo -----
__global__ __launch_bounds__(256) void wtrans_kernel(const float* __restrict__ W,
                                                     bf16* __restrict__ Th,
                                                     bf16* __restrict__ Tl,
                                                     int K, int N, size_t out_ls) {
    __shared__ float t[32][33];
    size_t inoff  = (size_t)blockIdx.z * K * N;
    size_t outoff = (size_t)blockIdx.z * out_ls;
    int k0 = blockIdx.y * 32, n0 = blockIdx.x * 32;
    int tx = threadIdx.x & 31, ty = threadIdx.x >> 5;
#pragma unroll
    for (int i = 0; i < 32; i += 8)
        t[ty + i][tx] = W[inoff + (size_t)(k0 + ty + i) * N + n0 + tx];
    __syncthreads();
#pragma unroll
    for (int i = 0; i < 32; i += 8) {
        float v = t[tx][ty + i];
        bf16 hi = __float2bfloat16(v);
        size_t idx = outoff + (size_t)(n0 + ty + i) * K + k0 + tx;
        Th[idx] = hi;
        Tl[idx] = __float2bfloat16(v - __bfloat162float(hi));
    }
}

// merged q/k/v transpose
__global__ __launch_bounds__(256) void wtransqkv_kernel(const float* __restrict__ wq,
                                                        const float* __restrict__ wk,
                                                        const float* __restrict__ wv,
                                                        bf16* __restrict__ Th,
                                                        bf16* __restrict__ Tl) {
    __shared__ float t[32][33];
    int z = blockIdx.z;
    int l = z / 3, which = z - l * 3;
    const float* W = (which == 0) ? wq : (which == 1) ? wk : wv;
    size_t inoff  = (size_t)l * D_ * D_;
    size_t outoff = (size_t)l * D3 * D_ + (size_t)which * D_ * D_;
    int k0 = blockIdx.y * 32, n0 = blockIdx.x * 32;
    int tx = threadIdx.x & 31, ty = threadIdx.x >> 5;
#pragma unroll
    for (int i = 0; i < 32; i += 8)
        t[ty + i][tx] = W[inoff + (size_t)(k0 + ty + i) * D_ + n0 + tx];
    __syncthreads();
#pragma unroll
    for (int i = 0; i < 32; i += 8) {
        float v = t[tx][ty + i];
        bf16 hi = __float2bfloat16(v);
        size_t idx = outoff + (size_t)(n0 + ty + i) * D_ + k0 + tx;
        Th[idx] = hi;
        Tl[idx] = __float2bfloat16(v - __bfloat162float(hi));
    }
}

// ---------------- LayerNorm: fp32 in -> bf16 hi/lo out -----------------------
__global__ __launch_bounds__(256) void ln_kernel(const float* __restrict__ x,
                                                 const float* __restrict__ g,
                                                 const float* __restrict__ b,
                                                 bf16* __restrict__ yh,
                                                 bf16* __restrict__ yl) {
    int row = blockIdx.x, tid = threadIdx.x;
    float4 f = *(const float4*)(x + (size_t)row * D_ + tid * 4);
    float s  = f.x + f.y + f.z + f.w;
    float ss = f.x*f.x + f.y*f.y + f.z*f.z + f.w*f.w;
#pragma unroll
    for (int o = 16; o > 0; o >>= 1) {
        s  += __shfl_xor_sync(0xffffffffu, s, o);
        ss += __shfl_xor_sync(0xffffffffu, ss, o);
    }
    __shared__ float rs[8], rss[8];
    if ((tid & 31) == 0) { rs[tid >> 5] = s; rss[tid >> 5] = ss; }
    __syncthreads();
    float ts = 0.f, tss = 0.f;
#pragma unroll
    for (int i = 0; i < 8; i++) { ts += rs[i]; tss += rss[i]; }
    float mean = ts * (1.0f / D_);
    float var  = tss * (1.0f / D_) - mean * mean;
    float r    = rsqrtf(var + 1e-6f);
    float4 g4 = *(const float4*)(g + tid * 4);
    float4 b4 = *(const float4*)(b + tid * 4);
    float o[4];
    o[0]=(f.x-mean)*r*g4.x+b4.x; o[1]=(f.y-mean)*r*g4.y+b4.y;
    o[2]=(f.z-mean)*r*g4.z+b4.z; o[3]=(f.w-mean)*r*g4.w+b4.w;
    size_t base = (size_t)row * D_ + tid * 4;
#pragma unroll
    for (int j = 0; j < 4; j += 2) {
        bf16 h0 = __float2bfloat16(o[j]);
        bf16 h1 = __float2bfloat16(o[j + 1]);
        *(__nv_bfloat162*)(yh + base + j) = __nv_bfloat162(h0, h1);
        *(__nv_bfloat162*)(yl + base + j) = __nv_bfloat162(
            __float2bfloat16(o[j] - __bfloat162float(h0)),
            __float2bfloat16(o[j + 1] - __bfloat162float(h1)));
    }
}

// ---------------- split-bf16 mma.sync GEMM 128x128, Kc=32, SW64, x3, occ2 ---
static constexpr int TILE32 = 128 * 32 * 2;
static constexpr int S_AH = 0, S_AL = TILE32, S_BH = 2 * TILE32, S_BL = 3 * TILE32;
static constexpr int STAGEB = 4 * TILE32;       // 32 KB
static constexpr int GEMM_SMEM = 3 * STAGEB;    // 96 KB -> 2 CTAs/SM

__device__ __forceinline__ void tile_cpa32(const bf16* __restrict__ g,
                                           int row0, int stride, int k0,
                                           uint32_t sdst, int tid) {
#pragma unroll
    for (int i = 0; i < 2; i++) {
        int idx = i * 256 + tid;
        int r = idx >> 2, c = idx & 3;
        CPA(sdst + swz64(r * 64 + c * 16), g + (size_t)(row0 + r) * stride + k0 + c * 8);
    }
}

__global__ __launch_bounds__(256, 2) void gemm_mma_kernel(
    const bf16* __restrict__ Ah, const bf16* __restrict__ Al,
    const bf16* __restrict__ Bh, const bf16* __restrict__ Bl,
    const float* __restrict__ bias, const float* __restrict__ r1,
    const float* __restrict__ r2, float* __restrict__ C,
    bf16* __restrict__ Ch, bf16* __restrict__ Cl,
    int NN, int KK, int act) {
    extern __shared__ char smem[];
    const uint32_t sb = smem_u32(smem);
    const int tid = threadIdx.x;
    const int wid = tid >> 5, lane = tid & 31;
    const int wm = wid >> 2, wn = wid & 3;
    const int rowBase = blockIdx.y * 128, colBase = blockIdx.x * 128;

    float acc[4][4][4];
#pragma unroll
    for (int i = 0; i < 4; i++)
#pragma unroll
        for (int j = 0; j < 4; j++)
#pragma unroll
            for (int q = 0; q < 4; q++) acc[i][j][q] = 0.f;

    const uint32_t a_row = (uint32_t)((wm * 64 + (lane & 15)) * 64);
    const uint32_t a_col = (uint32_t)((lane >> 4) * 16);
    const uint32_t b_row0 = (uint32_t)((wn * 32 + (lane & 7) + ((lane >> 4) << 3)) * 64);
    const uint32_t b_col = (uint32_t)(((lane >> 3) & 1) * 16);

    const int nc = KK / 32;
    tile_cpa32(Ah, rowBase, KK, 0, sb + S_AH, tid);
    tile_cpa32(Al, rowBase, KK, 0, sb + S_AL, tid);
    tile_cpa32(Bh, colBase, KK, 0, sb + S_BH, tid);
    tile_cpa32(Bl, colBase, KK, 0, sb + S_BL, tid);
    CPA_COMMIT();
    {
        uint32_t st = sb + STAGEB;
        tile_cpa32(Ah, rowBase, KK, 32, st + S_AH, tid);
        tile_cpa32(Al, rowBase, KK, 32, st + S_AL, tid);
        tile_cpa32(Bh, colBase, KK, 32, st + S_BH, tid);
        tile_cpa32(Bl, colBase, KK, 32, st + S_BL, tid);
    }
    CPA_COMMIT();

    for (int c = 0; c < nc; c++) {
        if (c + 1 < nc) CPA_WAIT1(); else CPA_WAIT0();
        __syncthreads();
        if (c + 2 < nc) {
            uint32_t st = sb + ((c + 2) % 3) * STAGEB;
            int k0 = (c + 2) * 32;
            tile_cpa32(Ah, rowBase, KK, k0, st + S_AH, tid);
            tile_cpa32(Al, rowBase, KK, k0, st + S_AL, tid);
            tile_cpa32(Bh, colBase, KK, k0, st + S_BH, tid);
            tile_cpa32(Bl, colBase, KK, k0, st + S_BL, tid);
            CPA_COMMIT();
        }
        uint32_t st = sb + (c % 3) * STAGEB;

#pragma unroll
        for (int ks = 0; ks < 2; ks++) {
            const uint32_t kb = ks * 32;
            uint32_t bh[2][4], bl[2][4];
#pragma unroll
            for (int g = 0; g < 2; g++) {
                uint32_t roff = b_row0 + (uint32_t)(g * 16 * 64);
                ldsm4(bh[g], st + S_BH + smx64(roff, kb + b_col));
                ldsm4(bl[g], st + S_BL + smx64(roff, kb + b_col));
            }
#pragma unroll
            for (int mi = 0; mi < 4; mi++) {
                uint32_t roff = a_row + (uint32_t)(mi * 16 * 64);
                uint32_t a_h[4], a_l[4];
                ldsm4(a_h, st + S_AH + smx64(roff, kb + a_col));
                ldsm4(a_l, st + S_AL + smx64(roff, kb + a_col));
                // term-major order: consecutive MMAs hit different accumulators
                // (per-acc accumulation order hh -> hl -> lh preserved: bit-identical)
#pragma unroll
                for (int t = 0; t < 3; t++) {
                    const uint32_t* af = (t == 2) ? a_l : a_h;
#pragma unroll
                    for (int nj = 0; nj < 4; nj++) {
                        int g = nj >> 1, o = (nj & 1) * 2;
                        uint32_t c0 = (t == 1) ? bl[g][o]     : bh[g][o];
                        uint32_t c1 = (t == 1) ? bl[g][o + 1] : bh[g][o + 1];
                        mma16816(acc[mi][nj], af, c0, c1);
                    }
                }
            }
        }
    }

    const int tq = lane >> 2, tr = lane & 3;
#pragma unroll
    for (int mi = 0; mi < 4; mi++) {
#pragma unroll
        for (int nj = 0; nj < 4; nj++) {
            int n = colBase + wn * 32 + nj * 8 + tr * 2;
            float2 bb = *(const float2*)(bias + n);
#pragma unroll
            for (int half = 0; half < 2; half++) {
                int m = rowBase + wm * 64 + mi * 16 + tq + half * 8;
                size_t base = (size_t)m * NN + n;
                float v0 = acc[mi][nj][half * 2 + 0] + bb.x;
                float v1 = acc[mi][nj][half * 2 + 1] + bb.y;
                if (act == 1) { v0 = v0 * normcdff(v0); v1 = v1 * normcdff(v1); }
                if (r1) { float2 q = *(const float2*)(r1 + base); v0 += q.x; v1 += q.y; }
                if (r2) { float2 q = *(const float2*)(r2 + base); v0 += q.x; v1 += q.y; }
                if (C) { float2 ov = {v0, v1}; *(float2*)(C + base) = ov; }
                if (Ch) {
                    bf16 h0 = __float2bfloat16(v0);
                    bf16 h1 = __float2bfloat16(v1);
                    *(__nv_bfloat162*)(Ch + base) = __nv_bfloat162(h0, h1);
                    *(__nv_bfloat162*)(Cl + base) = __nv_bfloat162(
                        __float2bfloat16(v0 - __bfloat162float(h0)),
                        __float2bfloat16(v1 - __bfloat162float(h1)));
                }
            }
        }
    }
}

// ---------------- tensor-core attention --------------------------------------
static constexpr int QT = 32;
static constexpr int SCS2 = 520;
static constexpr int AO_Q = 0, AO_KV = 8192, AO_SC = 40960;
static constexpr int AO_AWH = 107520, AO_AWL = 140800;
static constexpr int ATTN_SMEM = 174080;

__device__ __forceinline__ void tile64_cpa(const bf16* __restrict__ g,
                                           int row0, int stride, uint32_t sdst, int tid) {
#pragma unroll
    for (int i = 0; i < 2; i++) {
        int idx = i * 256 + tid;
        int r = idx >> 3, c = idx & 7;
        CPA(sdst + swz(r * 128 + c * 16), g + (size_t)(row0 + r) * stride + c * 8);
    }
}

__global__ __launch_bounds__(256, 1) void attn_mma_kernel(
    const bf16* __restrict__ qkvh, const bf16* __restrict__ qkvl,
    const float* __restrict__ bias,
    bf16* __restrict__ Ch, bf16* __restrict__ Cl) {
    extern __shared__ char smem[];
    const uint32_t sb = smem_u32(smem);
    const int tid = threadIdx.x;
    const int wid = tid >> 5, lane = tid & 31;
    const int wm = wid >> 2, wn = wid & 3;
    const int q0 = blockIdx.x * QT, h = blockIdx.y, b = blockIdx.z;
    const size_t base3 = (size_t)(b * S_) * D3 + h * DH_;
    const bf16* Qh = qkvh + base3;          const bf16* Ql = qkvl + base3;
    const bf16* Kh = qkvh + base3 + D_;     const bf16* Kl = qkvl + base3 + D_;
    const bf16* Vh = qkvh + base3 + 2*D_;   const bf16* Vl = qkvl + base3 + 2*D_;
    const int tq = lane >> 2, tr = lane & 3;

    {
        int r = tid >> 3, c = tid & 7;
        CPA(sb + AO_Q + swz(r * 128 + c * 16),        Qh + (size_t)(q0 + r) * D3 + c * 8);
        CPA(sb + AO_Q + 4096 + swz(r * 128 + c * 16), Ql + (size_t)(q0 + r) * D3 + c * 8);
    }
    tile64_cpa(Kh, 0, D3, sb + AO_KV, tid);
    tile64_cpa(Kl, 0, D3, sb + AO_KV + 8192, tid);
    CPA_COMMIT();
    CPA_WAIT0();
    __syncthreads();

    uint32_t qfh[4][4], qfl[4][4];
    {
        uint32_t arow = (uint32_t)((wm * 16 + (lane & 15)) * 128);
        uint32_t acol = (uint32_t)((lane >> 4) * 16);
#pragma unroll
        for (int ks = 0; ks < 4; ks++) {
            ldsm4(qfh[ks], sb + AO_Q + smx(arow, ks * 32 + acol));
            ldsm4(qfl[ks], sb + AO_Q + 4096 + smx(arow, ks * 32 + acol));
        }
    }

    const uint32_t b_row = (uint32_t)((wn * 16 + (lane & 7) + ((lane >> 4) << 3)) * 128);
    const uint32_t b_col = (uint32_t)(((lane >> 3) & 1) * 16);
    for (int c = 0; c < 8; c++) {
        if (c < 7) {
            uint32_t st = sb + AO_KV + ((c + 1) & 1) * 16384;
            tile64_cpa(Kh, (c + 1) * 64, D3, st, tid);
            tile64_cpa(Kl, (c + 1) * 64, D3, st + 8192, tid);
            CPA_COMMIT();
            CPA_WAIT1();
        } else {
            CPA_WAIT0();
        }
        __syncthreads();
        uint32_t st = sb + AO_KV + (c & 1) * 16384;

        float acc[2][4] = {};
#pragma unroll
        for (int ks = 0; ks < 4; ks++) {
            uint32_t cb = ks * 32 + b_col;
            uint32_t kh4[4], kl4[4];
            ldsm4(kh4, st + smx(b_row, cb));
            ldsm4(kl4, st + 8192 + smx(b_row, cb));
            // term-major (per-acc order qh*kh -> qh*kl -> ql*kh preserved)
#pragma unroll
            for (int t = 0; t < 3; t++) {
                const uint32_t* af = (t == 2) ? qfl[ks] : qfh[ks];
                const uint32_t* bf = (t == 1) ? kl4 : kh4;
#pragma unroll
                for (int nj = 0; nj < 2; nj++)
                    mma16816(acc[nj], af, bf[nj * 2], bf[nj * 2 + 1]);
            }
        }
        float* sc = (float*)(smem + AO_SC);
#pragma unroll
        for (int nj = 0; nj < 2; nj++) {
            int kg = c * 64 + wn * 16 + nj * 8 + tr * 2;
#pragma unroll
            for (int half = 0; half < 2; half++) {
                int m = wm * 16 + tq + half * 8;
                int rel = (q0 + m) - kg + (P_ - 1);
                sc[m * SCS2 + kg]     = acc[nj][half*2+0] * 0.125f + __ldg(&bias[rel * H_ + h]);
                sc[m * SCS2 + kg + 1] = acc[nj][half*2+1] * 0.125f + __ldg(&bias[(rel - 1) * H_ + h]);
            }
        }
        __syncthreads();
    }

    tile64_cpa(Vh, 0, D3, sb + AO_KV, tid);
    tile64_cpa(Vl, 0, D3, sb + AO_KV + 8192, tid);
    CPA_COMMIT();

    {
        float* sc = (float*)(smem + AO_SC);
        bf16* awh = (bf16*)(smem + AO_AWH);
        bf16* awl = (bf16*)(smem + AO_AWL);
#pragma unroll
        for (int rr = 0; rr < 4; rr++) {
            int r = wid * 4 + rr;
            float* row = sc + r * SCS2;
            float mx = -1e30f;
            for (int cc = lane; cc < S_; cc += 32) mx = fmaxf(mx, row[cc]);
#pragma unroll
            for (int o = 16; o > 0; o >>= 1) mx = fmaxf(mx, __shfl_xor_sync(0xffffffffu, mx, o));
            float sum = 0.f;
            for (int cc = lane; cc < S_; cc += 32) {
                float e = expf(row[cc] - mx);
                row[cc] = e;
                sum += e;
            }
#pragma unroll
            for (int o = 16; o > 0; o >>= 1) sum += __shfl_xor_sync(0xffffffffu, sum, o);
            float inv = 1.0f / sum;
            for (int cc = lane; cc < S_; cc += 32) {
                float a = row[cc] * inv;
                bf16 hi = __float2bfloat16(a);
                awh[r * SCS2 + cc] = hi;
                awl[r * SCS2 + cc] = __float2bfloat16(a - __bfloat162float(hi));
            }
        }
    }
    __syncthreads();

    float cacc[2][4] = {};
    const uint32_t aw_row = (uint32_t)((wm * 16 + (lane & 15)) * (SCS2 * 2));
    const uint32_t v_row = (uint32_t)(((lane & 7) + ((lane >> 3) & 1) * 8) * 128);
    const uint32_t v_col = (uint32_t)(wn * 32 + (lane >> 4) * 16);
    for (int c = 0; c < 8; c++) {
        if (c < 7) {
            uint32_t st = sb + AO_KV + ((c + 1) & 1) * 16384;
            tile64_cpa(Vh, (c + 1) * 64, D3, st, tid);
            tile64_cpa(Vl, (c + 1) * 64, D3, st + 8192, tid);
            CPA_COMMIT();
            CPA_WAIT1();
        } else {
            CPA_WAIT0();
        }
        __syncthreads();
        uint32_t st = sb + AO_KV + (c & 1) * 16384;

#pragma unroll
        for (int ks = 0; ks < 4; ks++) {
            uint32_t awoff = aw_row + (uint32_t)((c * 64 + ks * 16 + (lane >> 4) * 8) * 2);
            uint32_t ah4[4], al4[4];
            ldsm4(ah4, sb + AO_AWH + awoff);
            ldsm4(al4, sb + AO_AWL + awoff);
            uint32_t vro = v_row + (uint32_t)(ks * 16 * 128);
            uint32_t vh4[4], vl4[4];
            ldsm4t(vh4, st + smx(vro, v_col));
            ldsm4t(vl4, st + 8192 + smx(vro, v_col));
#pragma unroll
            for (int t = 0; t < 3; t++) {
                const uint32_t* af = (t == 2) ? al4 : ah4;
                const uint32_t* vf = (t == 1) ? vl4 : vh4;
#pragma unroll
                for (int nj = 0; nj < 2; nj++)
                    mma16816(cacc[nj], af, vf[nj * 2], vf[nj * 2 + 1]);
            }
        }
        __syncthreads();
    }

#pragma unroll
    for (int nj = 0; nj < 2; nj++) {
        int n = wn * 16 + nj * 8 + tr * 2;
#pragma unroll
        for (int half = 0; half < 2; half++) {
            int m = wm * 16 + tq + half * 8;
            size_t gidx = (size_t)(b * S_ + q0 + m) * D_ + h * DH_ + n;
            float v0 = cacc[nj][half*2+0];
            float v1 = cacc[nj][half*2+1];
            bf16 h0 = __float2bfloat16(v0);
            bf16 h1 = __float2bfloat16(v1);
            *(__nv_bfloat162*)(Ch + gidx) = __nv_bfloat162(h0, h1);
            *(__nv_bfloat162*)(Cl + gidx) = __nv_bfloat162(
                __float2bfloat16(v0 - __bfloat162float(h0)),
                __float2bfloat16(v1 - __bfloat162float(h1)));
        }
    }
}

// ---------------- launch ----------------------------------------------------
extern "C" void kernel_launch(void* const* d_in, const int* in_sizes, int n_in,
                              void* d_out, int out_size) {
    (void)in_sizes; (void)n_in; (void)out_size;
    const float* x    = (const float*)d_in[0];
    const float* pe   = (const float*)d_in[1];
    const float* wq   = (const float*)d_in[2];
    const float* bq   = (const float*)d_in[3];
    const float* wk   = (const float*)d_in[4];
    const float* bk   = (const float*)d_in[5];
    const float* wv   = (const float*)d_in[6];
    const float* bv   = (const float*)d_in[7];
    const float* wo   = (const float*)d_in[8];
    const float* bo   = (const float*)d_in[9];
    const float* bt   = (const float*)d_in[10];
    const float* w1   = (const float*)d_in[11];
    const float* b1   = (const float*)d_in[12];
    const float* w2   = (const float*)d_in[13];
    const float* b2   = (const float*)d_in[14];
    const float* ln1g = (const float*)d_in[15];
    const float* ln1b = (const float*)d_in[16];
    const float* ln2g = (const float*)d_in[17];
    const float* ln2b = (const float*)d_in[18];
    float* out = (float*)d_out;

    float *hb, *o1, *bqkv;
    bf16 *xnh, *xnl, *qkvh, *qkvl, *cxh, *cxl, *f1h, *f1l;
    bf16 *wqkvhp, *wqkvlp, *woh, *wol, *w1h, *w1l, *w2h, *w2l;
    cudaGetSymbolAddress((void**)&hb,   g_h);
    cudaGetSymbolAddress((void**)&o1,   g_out1);
    cudaGetSymbolAddress((void**)&bqkv, g_bqkv);
    cudaGetSymbolAddress((void**)&xnh,  g_xn_h);  cudaGetSymbolAddress((void**)&xnl, g_xn_l);
    cudaGetSymbolAddress((void**)&qkvh, g_qkv_h); cudaGetSymbolAddress((void**)&qkvl, g_qkv_l);
    cudaGetSymbolAddress((void**)&cxh,  g_ctx_h); cudaGetSymbolAddress((void**)&cxl, g_ctx_l);
    cudaGetSymbolAddress((void**)&f1h,  g_f1_h);  cudaGetSymbolAddress((void**)&f1l, g_f1_l);
    cudaGetSymbolAddress((void**)&wqkvhp, g_wqkvT_h); cudaGetSymbolAddress((void**)&wqkvlp, g_wqkvT_l);
    cudaGetSymbolAddress((void**)&woh,  g_woT_h); cudaGetSymbolAddress((void**)&wol, g_woT_l);
    cudaGetSymbolAddress((void**)&w1h,  g_w1T_h); cudaGetSymbolAddress((void**)&w1l, g_w1T_l);
    cudaGetSymbolAddress((void**)&w2h,  g_w2T_h); cudaGetSymbolAddress((void**)&w2l, g_w2T_l);

    cudaFuncSetAttribute(attn_mma_kernel, cudaFuncAttributeMaxDynamicSharedMemorySize, ATTN_SMEM);
    cudaFuncSetAttribute(gemm_mma_kernel, cudaFuncAttributeMaxDynamicSharedMemorySize, GEMM_SMEM);

    dim3 gQKV(D3 / 128, M_ / 128);
    dim3 gD(D_ / 128, M_ / 128);
    dim3 gF(F_ / 128, M_ / 128);
    dim3 gAttn(S_ / QT, H_, B_);

    addpe_kernel<<<(M_ * D_) / 256, 256>>>(x, pe, hb);
    packb_kernel<<<dim3(D_ / 256, L_), 256>>>(bq, bk, bv, bqkv);
    wtransqkv_kernel<<<dim3(32, 32, 3 * L_), 256>>>(wq, wk, wv, wqkvhp, wqkvlp);
    wtrans_kernel<<<dim3(32, 32, L_), 256>>>(wo, woh, wol, D_, D_, (size_t)D_ * D_);
    wtrans_kernel<<<dim3(F_ / 32, D_ / 32, L_), 256>>>(w1, w1h, w1l, D_, F_, (size_t)D_ * F_);
    wtrans_kernel<<<dim3(D_ / 32, F_ / 32, L_), 256>>>(w2, w2h, w2l, F_, D_, (size_t)F_ * D_);

    for (int l = 0; l < L_; l++) {
        size_t oQKV = (size_t)l * D3 * D_;
        size_t oDD  = (size_t)l * D_ * D_;
        size_t oDF  = (size_t)l * D_ * F_;
        size_t oD   = (size_t)l * D_;
        size_t oF   = (size_t)l * F_;

        ln_kernel<<<M_, 256>>>(hb, ln1g + oD, ln1b + oD, xnh, xnl);
        gemm_mma_kernel<<<gQKV, 256, GEMM_SMEM>>>(xnh, xnl, wqkvhp + oQKV, wqkvlp + oQKV,
            bqkv + (size_t)l * D3, nullptr, nullptr, nullptr, qkvh, qkvl, D3, D_, 0);

        attn_mma_kernel<<<gAttn, 256, ATTN_SMEM>>>(qkvh, qkvl,
            bt + (size_t)l * (2 * P_ - 1) * H_, cxh, cxl);

        gemm_mma_kernel<<<gD, 256, GEMM_SMEM>>>(cxh, cxl, woh + oDD, wol + oDD,
            bo + oD, hb, nullptr, o1, nullptr, nullptr, D_, D_, 0);

        ln_kernel<<<M_, 256>>>(o1, ln2g + oD, ln2b + oD, xnh, xnl);
        gemm_mma_kernel<<<gF, 256, GEMM_SMEM>>>(xnh, xnl, w1h + oDF, w1l + oDF,
            b1 + oF, nullptr, nullptr, nullptr, f1h, f1l, F_, D_, 1);
        float* dst = (l == L_ - 1) ? out : hb;
        gemm_mma_kernel<<<gD, 256, GEMM_SMEM>>>(f1h, f1l, w2h + oDF, w2l + oDF,
            b2 + oD, o1, hb, dst, nullptr, nullptr, D_, F_, 0);
    }
}

// round 12
// speedup vs baseline: 3.0327x; 1.3191x over previous
#include <cuda_runtime.h>
#include <cuda_fp16.h>
#include <math.h>
#include <cstdint>

using fp16 = __half;

static constexpr int L_ = 6, D_ = 1024, H_ = 16, F_ = 4096, S_ = 512, B_ = 16, P_ = 512;
static constexpr int DH_ = D_ / H_;
static constexpr int M_ = B_ * S_;
static constexpr int D3 = 3 * D_;

// ---------------- scratch ----------------------------------------------------
__device__ __align__(16) float g_h[(size_t)M_ * D_];
__device__ __align__(16) float g_out1[(size_t)M_ * D_];

__device__ __align__(16) fp16 g_xn_h[(size_t)M_ * D_];
__device__ __align__(16) fp16 g_xn_l[(size_t)M_ * D_];
__device__ __align__(16) fp16 g_qkv_h[(size_t)M_ * D3];
__device__ __align__(16) fp16 g_qkv_l[(size_t)M_ * D3];
__device__ __align__(16) fp16 g_ctx_h[(size_t)M_ * D_];
__device__ __align__(16) fp16 g_ctx_l[(size_t)M_ * D_];
__device__ __align__(16) fp16 g_f1_h[(size_t)M_ * F_];
__device__ __align__(16) fp16 g_f1_l[(size_t)M_ * F_];

// single-plane fp16 weights [N,K]
__device__ __align__(16) fp16 g_wqkvT[(size_t)L_ * D3 * D_];
__device__ __align__(16) fp16 g_woT[(size_t)L_ * D_ * D_];
__device__ __align__(16) fp16 g_w1T[(size_t)L_ * D_ * F_];
__device__ __align__(16) fp16 g_w2T[(size_t)L_ * F_ * D_];
__device__ __align__(16) float g_bqkv[(size_t)L_ * D3];

// ---------------- PTX helpers -------------------------------------------------
__device__ __forceinline__ uint32_t smem_u32(const void* p) {
    uint32_t a;
    asm("{ .reg .u64 t; cvta.to.shared.u64 t, %1; cvt.u32.u64 %0, t; }" : "=r"(a) : "l"(p));
    return a;
}
__device__ __forceinline__ void ldsm4(uint32_t* r, uint32_t addr) {
    asm volatile("ldmatrix.sync.aligned.m8n8.x4.shared.b16 {%0,%1,%2,%3}, [%4];"
                 : "=r"(r[0]), "=r"(r[1]), "=r"(r[2]), "=r"(r[3]) : "r"(addr));
}
__device__ __forceinline__ void ldsm4t(uint32_t* r, uint32_t addr) {
    asm volatile("ldmatrix.sync.aligned.m8n8.x4.trans.shared.b16 {%0,%1,%2,%3}, [%4];"
                 : "=r"(r[0]), "=r"(r[1]), "=r"(r[2]), "=r"(r[3]) : "r"(addr));
}
__device__ __forceinline__ void mma16816h(float* d, const uint32_t* a, uint32_t b0, uint32_t b1) {
    asm volatile("mma.sync.aligned.m16n8k16.row.col.f32.f16.f16.f32 "
                 "{%0,%1,%2,%3}, {%4,%5,%6,%7}, {%8,%9}, {%0,%1,%2,%3};"
                 : "+f"(d[0]), "+f"(d[1]), "+f"(d[2]), "+f"(d[3])
                 : "r"(a[0]), "r"(a[1]), "r"(a[2]), "r"(a[3]), "r"(b0), "r"(b1));
}
#define CPA(dst, src)  asm volatile("cp.async.cg.shared.global [%0], [%1], 16;" :: "r"(dst), "l"(src))
#define CPA_COMMIT()   asm volatile("cp.async.commit_group;" ::: "memory")
#define CPA_WAIT1()    asm volatile("cp.async.wait_group 1;" ::: "memory")
#define CPA_WAIT0()    asm volatile("cp.async.wait_group 0;" ::: "memory")

__device__ __forceinline__ uint32_t swz(uint32_t off)   { return off ^ ((off >> 3) & 0x70); }
__device__ __forceinline__ uint32_t swz64(uint32_t off) { return off ^ ((off >> 3) & 0x30); }
__device__ __forceinline__ uint32_t smx(uint32_t r, uint32_t c)   { return r + (c ^ ((r >> 3) & 0x70)); }
__device__ __forceinline__ uint32_t smx64(uint32_t r, uint32_t c) { return r + (c ^ ((r >> 3) & 0x30)); }

__device__ __forceinline__ __half2 split_hi(float a, float b) {
    return __halves2half2(__float2half_rn(a), __float2half_rn(b));
}
__device__ __forceinline__ __half2 split_lo(float a, float b, __half2 hi) {
    return __halves2half2(__float2half_rn(a - __half2float(__low2half(hi))),
                          __float2half_rn(b - __half2float(__high2half(hi))));
}

// ---------------- h = x + pe -------------------------------------------------
__global__ __launch_bounds__(256) void addpe_kernel(const float* __restrict__ x,
                                                    const float* __restrict__ pe,
                                                    float* __restrict__ h) {
    int i = blockIdx.x * 256 + threadIdx.x;
    h[i] = x[i] + pe[i & (S_ * D_ - 1)];
}

// ---------------- pack qkv bias ----------------------------------------------
__global__ __launch_bounds__(256) void packb_kernel(const float* __restrict__ bq,
                                                    const float* __restrict__ bk,
                                                    const float* __restrict__ bv,
                                                    float* __restrict__ o) {
    int l = blockIdx.y;
    int i = blockIdx.x * 256 + threadIdx.x;
    o[(size_t)l * D3 + i]          = bq[l * D_ + i];
    o[(size_t)l * D3 + D_ + i]     = bk[l * D_ + i];
    o[(size_t)l * D3 + 2 * D_ + i] = bv[l * D_ + i];
}

// ---------------- weight transpose: W[K,N] -> T[N,K] fp16 --------------------
__global__ __launch_bounds__(256) void wtrans_kernel(const float* __restrict__ W,
                                                     fp16* __restrict__ T,
                                                     int K, int N, size_t out_ls) {
    __shared__ float t[32][33];
    size_t inoff  = (size_t)blockIdx.z * K * N;
    size_t outoff = (size_t)blockIdx.z * out_ls;
    int k0 = blockIdx.y * 32, n0 = blockIdx.x * 32;
    int tx = threadIdx.x & 31, ty = threadIdx.x >> 5;
#pragma unroll
    for (int i = 0; i < 32; i += 8)
        t[ty + i][tx] = W[inoff + (size_t)(k0 + ty + i) * N + n0 + tx];
    __syncthreads();
#pragma unroll
    for (int i = 0; i < 32; i += 8)
        T[outoff + (size_t)(n0 + ty + i) * K + k0 + tx] = __float2half_rn(t[tx][ty + i]);
}

// merged q/k/v transpose -> fused [D3,K] fp16
__global__ __launch_bounds__(256) void wtransqkv_kernel(const float* __restrict__ wq,
                                                        const float* __restrict__ wk,
                                                        const float* __restrict__ wv,
                                                        fp16* __restrict__ T) {
    __shared__ float t[32][33];
    int z = blockIdx.z;
    int l = z / 3, which = z - l * 3;
    const float* W = (which == 0) ? wq : (which == 1) ? wk : wv;
    size_t inoff  = (size_t)l * D_ * D_;
    size_t outoff = (size_t)l * D3 * D_ + (size_t)which * D_ * D_;
    int k0 = blockIdx.y * 32, n0 = blockIdx.x * 32;
    int tx = threadIdx.x & 31, ty = threadIdx.x >> 5;
#pragma unroll
    for (int i = 0; i < 32; i += 8)
        t[ty + i][tx] = W[inoff + (size_t)(k0 + ty + i) * D_ + n0 + tx];
    __syncthreads();
#pragma unroll
    for (int i = 0; i < 32; i += 8)
        T[outoff + (size_t)(n0 + ty + i) * D_ + k0 + tx] = __float2half_rn(t[tx][ty + i]);
}

// ---------------- LayerNorm: fp32 in -> fp16 hi/lo out -----------------------
__global__ __launch_bounds__(256) void ln_kernel(const float* __restrict__ x,
                                                 const float* __restrict__ g,
                                                 const float* __restrict__ b,
                                                 fp16* __restrict__ yh,
                                                 fp16* __restrict__ yl) {
    int row = blockIdx.x, tid = threadIdx.x;
    float4 f = *(const float4*)(x + (size_t)row * D_ + tid * 4);
    float s  = f.x + f.y + f.z + f.w;
    float ss = f.x*f.x + f.y*f.y + f.z*f.z + f.w*f.w;
#pragma unroll
    for (int o = 16; o > 0; o >>= 1) {
        s  += __shfl_xor_sync(0xffffffffu, s, o);
        ss += __shfl_xor_sync(0xffffffffu, ss, o);
    }
    __shared__ float rs[8], rss[8];
    if ((tid & 31) == 0) { rs[tid >> 5] = s; rss[tid >> 5] = ss; }
    __syncthreads();
    float ts = 0.f, tss = 0.f;
#pragma unroll
    for (int i = 0; i < 8; i++) { ts += rs[i]; tss += rss[i]; }
    float mean = ts * (1.0f / D_);
    float var  = tss * (1.0f / D_) - mean * mean;
    float r    = rsqrtf(var + 1e-6f);
    float4 g4 = *(const float4*)(g + tid * 4);
    float4 b4 = *(const float4*)(b + tid * 4);
    float o[4];
    o[0]=(f.x-mean)*r*g4.x+b4.x; o[1]=(f.y-mean)*r*g4.y+b4.y;
    o[2]=(f.z-mean)*r*g4.z+b4.z; o[3]=(f.w-mean)*r*g4.w+b4.w;
    size_t base = (size_t)row * D_ + tid * 4;
#pragma unroll
    for (int j = 0; j < 4; j += 2) {
        __half2 hv = split_hi(o[j], o[j + 1]);
        *(__half2*)(yh + base + j) = hv;
        *(__half2*)(yl + base + j) = split_lo(o[j], o[j + 1], hv);
    }
}

// ---------------- 2-term fp16 mma.sync GEMM 128x128, Kc=32, SW64, x3, occ2 --
// C = act((Ah+Al)@Bh^T + bias) + r1 + r2
static constexpr int TILE32 = 128 * 32 * 2;     // 8 KB
static constexpr int S_AH = 0, S_AL = TILE32, S_B = 2 * TILE32;
static constexpr int STAGEB = 3 * TILE32;       // 24 KB
static constexpr int GEMM_SMEM = 3 * STAGEB;    // 72 KB -> 2 CTAs/SM

__device__ __forceinline__ void tile_cpa32(const fp16* __restrict__ g,
                                           int row0, int stride, int k0,
                                           uint32_t sdst, int tid) {
#pragma unroll
    for (int i = 0; i < 2; i++) {
        int idx = i * 256 + tid;
        int r = idx >> 2, c = idx & 3;
        CPA(sdst + swz64(r * 64 + c * 16), g + (size_t)(row0 + r) * stride + k0 + c * 8);
    }
}

__global__ __launch_bounds__(256, 2) void gemm_mma_kernel(
    const fp16* __restrict__ Ah, const fp16* __restrict__ Al,
    const fp16* __restrict__ Bh,
    const float* __restrict__ bias, const float* __restrict__ r1,
    const float* __restrict__ r2, float* __restrict__ C,
    fp16* __restrict__ Ch, fp16* __restrict__ Cl,
    int NN, int KK, int act) {
    extern __shared__ char smem[];
    const uint32_t sb = smem_u32(smem);
    const int tid = threadIdx.x;
    const int wid = tid >> 5, lane = tid & 31;
    const int wm = wid >> 2, wn = wid & 3;
    const int rowBase = blockIdx.y * 128, colBase = blockIdx.x * 128;

    float acc[4][4][4];
#pragma unroll
    for (int i = 0; i < 4; i++)
#pragma unroll
        for (int j = 0; j < 4; j++)
#pragma unroll
            for (int q = 0; q < 4; q++) acc[i][j][q] = 0.f;

    const uint32_t a_row = (uint32_t)((wm * 64 + (lane & 15)) * 64);
    const uint32_t a_col = (uint32_t)((lane >> 4) * 16);
    const uint32_t b_row0 = (uint32_t)((wn * 32 + (lane & 7) + ((lane >> 4) << 3)) * 64);
    const uint32_t b_col = (uint32_t)(((lane >> 3) & 1) * 16);

    const int nc = KK / 32;
    tile_cpa32(Ah, rowBase, KK, 0, sb + S_AH, tid);
    tile_cpa32(Al, rowBase, KK, 0, sb + S_AL, tid);
    tile_cpa32(Bh, colBase, KK, 0, sb + S_B,  tid);
    CPA_COMMIT();
    {
        uint32_t st = sb + STAGEB;
        tile_cpa32(Ah, rowBase, KK, 32, st + S_AH, tid);
        tile_cpa32(Al, rowBase, KK, 32, st + S_AL, tid);
        tile_cpa32(Bh, colBase, KK, 32, st + S_B,  tid);
    }
    CPA_COMMIT();

    for (int c = 0; c < nc; c++) {
        if (c + 1 < nc) CPA_WAIT1(); else CPA_WAIT0();
        __syncthreads();
        if (c + 2 < nc) {
            uint32_t st = sb + ((c + 2) % 3) * STAGEB;
            int k0 = (c + 2) * 32;
            tile_cpa32(Ah, rowBase, KK, k0, st + S_AH, tid);
            tile_cpa32(Al, rowBase, KK, k0, st + S_AL, tid);
            tile_cpa32(Bh, colBase, KK, k0, st + S_B,  tid);
            CPA_COMMIT();
        }
        uint32_t st = sb + (c % 3) * STAGEB;

#pragma unroll
        for (int ks = 0; ks < 2; ks++) {
            const uint32_t kb = ks * 32;
            uint32_t bh[2][4];
#pragma unroll
            for (int g = 0; g < 2; g++) {
                uint32_t roff = b_row0 + (uint32_t)(g * 16 * 64);
                ldsm4(bh[g], st + S_B + smx64(roff, kb + b_col));
            }
#pragma unroll
            for (int mi = 0; mi < 4; mi++) {
                uint32_t roff = a_row + (uint32_t)(mi * 16 * 64);
                uint32_t a_h[4], a_l[4];
                ldsm4(a_h, st + S_AH + smx64(roff, kb + a_col));
                ldsm4(a_l, st + S_AL + smx64(roff, kb + a_col));
#pragma unroll
                for (int nj = 0; nj < 4; nj++) {
                    int g = nj >> 1, o = (nj & 1) * 2;
                    mma16816h(acc[mi][nj], a_h, bh[g][o], bh[g][o + 1]);
                }
#pragma unroll
                for (int nj = 0; nj < 4; nj++) {
                    int g = nj >> 1, o = (nj & 1) * 2;
                    mma16816h(acc[mi][nj], a_l, bh[g][o], bh[g][o + 1]);
                }
            }
        }
    }

    const int tq = lane >> 2, tr = lane & 3;
#pragma unroll
    for (int mi = 0; mi < 4; mi++) {
#pragma unroll
        for (int nj = 0; nj < 4; nj++) {
            int n = colBase + wn * 32 + nj * 8 + tr * 2;
            float2 bb = *(const float2*)(bias + n);
#pragma unroll
            for (int half = 0; half < 2; half++) {
                int m = rowBase + wm * 64 + mi * 16 + tq + half * 8;
                size_t base = (size_t)m * NN + n;
                float v0 = acc[mi][nj][half * 2 + 0] + bb.x;
                float v1 = acc[mi][nj][half * 2 + 1] + bb.y;
                if (act == 1) { v0 = v0 * normcdff(v0); v1 = v1 * normcdff(v1); }
                if (r1) { float2 q = *(const float2*)(r1 + base); v0 += q.x; v1 += q.y; }
                if (r2) { float2 q = *(const float2*)(r2 + base); v0 += q.x; v1 += q.y; }
                if (C) { float2 ov = {v0, v1}; *(float2*)(C + base) = ov; }
                if (Ch) {
                    __half2 hv = split_hi(v0, v1);
                    *(__half2*)(Ch + base) = hv;
                    *(__half2*)(Cl + base) = split_lo(v0, v1, hv);
                }
            }
        }
    }
}

// ---------------- tensor-core attention (2-term fp16) ------------------------
static constexpr int QT = 32;
static constexpr int SCS2 = 520;
static constexpr int AO_Q = 0;                 // qh 4096 | ql 4096
static constexpr int AO_KV = 8192;             // 2 stages x 8192 (single plane)
static constexpr int AO_SC = 24576;            // 32*520*4 = 66560
static constexpr int AO_AWH = 91136;           // 33280
static constexpr int AO_AWL = 124416;          // 33280
static constexpr int ATTN_SMEM = 157696;

__device__ __forceinline__ void tile64_cpa(const fp16* __restrict__ g,
                                           int row0, int stride, uint32_t sdst, int tid) {
#pragma unroll
    for (int i = 0; i < 2; i++) {
        int idx = i * 256 + tid;
        int r = idx >> 3, c = idx & 7;
        CPA(sdst + swz(r * 128 + c * 16), g + (size_t)(row0 + r) * stride + c * 8);
    }
}

__global__ __launch_bounds__(256, 1) void attn_mma_kernel(
    const fp16* __restrict__ qkvh, const fp16* __restrict__ qkvl,
    const float* __restrict__ bias,
    fp16* __restrict__ Ch, fp16* __restrict__ Cl) {
    extern __shared__ char smem[];
    const uint32_t sb = smem_u32(smem);
    const int tid = threadIdx.x;
    const int wid = tid >> 5, lane = tid & 31;
    const int wm = wid >> 2, wn = wid & 3;
    const int q0 = blockIdx.x * QT, h = blockIdx.y, b = blockIdx.z;
    const size_t base3 = (size_t)(b * S_) * D3 + h * DH_;
    const fp16* Qh = qkvh + base3;          const fp16* Ql = qkvl + base3;
    const fp16* Kh = qkvh + base3 + D_;
    const fp16* Vh = qkvh + base3 + 2 * D_;
    const int tq = lane >> 2, tr = lane & 3;

    {
        int r = tid >> 3, c = tid & 7;
        CPA(sb + AO_Q + swz(r * 128 + c * 16),        Qh + (size_t)(q0 + r) * D3 + c * 8);
        CPA(sb + AO_Q + 4096 + swz(r * 128 + c * 16), Ql + (size_t)(q0 + r) * D3 + c * 8);
    }
    tile64_cpa(Kh, 0, D3, sb + AO_KV, tid);
    CPA_COMMIT();
    CPA_WAIT0();
    __syncthreads();

    uint32_t qfh[4][4], qfl[4][4];
    {
        uint32_t arow = (uint32_t)((wm * 16 + (lane & 15)) * 128);
        uint32_t acol = (uint32_t)((lane >> 4) * 16);
#pragma unroll
        for (int ks = 0; ks < 4; ks++) {
            ldsm4(qfh[ks], sb + AO_Q + smx(arow, ks * 32 + acol));
            ldsm4(qfl[ks], sb + AO_Q + 4096 + smx(arow, ks * 32 + acol));
        }
    }

    const uint32_t b_row = (uint32_t)((wn * 16 + (lane & 7) + ((lane >> 4) << 3)) * 128);
    const uint32_t b_col = (uint32_t)(((lane >> 3) & 1) * 16);
    for (int c = 0; c < 8; c++) {
        if (c < 7) {
            uint32_t st = sb + AO_KV + ((c + 1) & 1) * 8192;
            tile64_cpa(Kh, (c + 1) * 64, D3, st, tid);
            CPA_COMMIT();
            CPA_WAIT1();
        } else {
            CPA_WAIT0();
        }
        __syncthreads();
        uint32_t st = sb + AO_KV + (c & 1) * 8192;

        float acc[2][4] = {};
#pragma unroll
        for (int ks = 0; ks < 4; ks++) {
            uint32_t kh4[4];
            ldsm4(kh4, st + smx(b_row, ks * 32 + b_col));
#pragma unroll
            for (int nj = 0; nj < 2; nj++) {
                mma16816h(acc[nj], qfh[ks], kh4[nj * 2], kh4[nj * 2 + 1]);
                mma16816h(acc[nj], qfl[ks], kh4[nj * 2], kh4[nj * 2 + 1]);
            }
        }
        float* sc = (float*)(smem + AO_SC);
#pragma unroll
        for (int nj = 0; nj < 2; nj++) {
            int kg = c * 64 + wn * 16 + nj * 8 + tr * 2;
#pragma unroll
            for (int half = 0; half < 2; half++) {
                int m = wm * 16 + tq + half * 8;
                int rel = (q0 + m) - kg + (P_ - 1);
                sc[m * SCS2 + kg]     = acc[nj][half*2+0] * 0.125f + __ldg(&bias[rel * H_ + h]);
                sc[m * SCS2 + kg + 1] = acc[nj][half*2+1] * 0.125f + __ldg(&bias[(rel - 1) * H_ + h]);
            }
        }
        __syncthreads();
    }

    tile64_cpa(Vh, 0, D3, sb + AO_KV, tid);
    CPA_COMMIT();

    {
        float* sc = (float*)(smem + AO_SC);
        fp16* awh = (fp16*)(smem + AO_AWH);
        fp16* awl = (fp16*)(smem + AO_AWL);
#pragma unroll
        for (int rr = 0; rr < 4; rr++) {
            int r = wid * 4 + rr;
            float* row = sc + r * SCS2;
            float mx = -1e30f;
            for (int cc = lane; cc < S_; cc += 32) mx = fmaxf(mx, row[cc]);
#pragma unroll
            for (int o = 16; o > 0; o >>= 1) mx = fmaxf(mx, __shfl_xor_sync(0xffffffffu, mx, o));
            float sum = 0.f;
            for (int cc = lane; cc < S_; cc += 32) {
                float e = expf(row[cc] - mx);
                row[cc] = e;
                sum += e;
            }
#pragma unroll
            for (int o = 16; o > 0; o >>= 1) sum += __shfl_xor_sync(0xffffffffu, sum, o);
            float inv = 1.0f / sum;
            for (int cc = lane; cc < S_; cc += 32) {
                float a = row[cc] * inv;
                fp16 hi = __float2half_rn(a);
                awh[r * SCS2 + cc] = hi;
                awl[r * SCS2 + cc] = __float2half_rn(a - __half2float(hi));
            }
        }
    }
    __syncthreads();

    float cacc[2][4] = {};
    const uint32_t aw_row = (uint32_t)((wm * 16 + (lane & 15)) * (SCS2 * 2));
    const uint32_t v_row = (uint32_t)(((lane & 7) + ((lane >> 3) & 1) * 8) * 128);
    const uint32_t v_col = (uint32_t)(wn * 32 + (lane >> 4) * 16);
    for (int c = 0; c < 8; c++) {
        if (c < 7) {
            uint32_t st = sb + AO_KV + ((c + 1) & 1) * 8192;
            tile64_cpa(Vh, (c + 1) * 64, D3, st, tid);
            CPA_COMMIT();
            CPA_WAIT1();
        } else {
            CPA_WAIT0();
        }
        __syncthreads();
        uint32_t st = sb + AO_KV + (c & 1) * 8192;

#pragma unroll
        for (int ks = 0; ks < 4; ks++) {
            uint32_t awoff = aw_row + (uint32_t)((c * 64 + ks * 16 + (lane >> 4) * 8) * 2);
            uint32_t ah4[4], al4[4];
            ldsm4(ah4, sb + AO_AWH + awoff);
            ldsm4(al4, sb + AO_AWL + awoff);
            uint32_t vh4[4];
            ldsm4t(vh4, st + smx(v_row + (uint32_t)(ks * 16 * 128), v_col));
#pragma unroll
            for (int nj = 0; nj < 2; nj++) {
                mma16816h(cacc[nj], ah4, vh4[nj * 2], vh4[nj * 2 + 1]);
                mma16816h(cacc[nj], al4, vh4[nj * 2], vh4[nj * 2 + 1]);
            }
        }
        __syncthreads();
    }

#pragma unroll
    for (int nj = 0; nj < 2; nj++) {
        int n = wn * 16 + nj * 8 + tr * 2;
#pragma unroll
        for (int half = 0; half < 2; half++) {
            int m = wm * 16 + tq + half * 8;
            size_t gidx = (size_t)(b * S_ + q0 + m) * D_ + h * DH_ + n;
            float v0 = cacc[nj][half*2+0];
            float v1 = cacc[nj][half*2+1];
            __half2 hv = split_hi(v0, v1);
            *(__half2*)(Ch + gidx) = hv;
            *(__half2*)(Cl + gidx) = split_lo(v0, v1, hv);
        }
    }
}

// ---------------- launch ----------------------------------------------------
extern "C" void kernel_launch(void* const* d_in, const int* in_sizes, int n_in,
                              void* d_out, int out_size) {
    (void)in_sizes; (void)n_in; (void)out_size;
    const float* x    = (const float*)d_in[0];
    const float* pe   = (const float*)d_in[1];
    const float* wq   = (const float*)d_in[2];
    const float* bq   = (const float*)d_in[3];
    const float* wk   = (const float*)d_in[4];
    const float* bk   = (const float*)d_in[5];
    const float* wv   = (const float*)d_in[6];
    const float* bv   = (const float*)d_in[7];
    const float* wo   = (const float*)d_in[8];
    const float* bo   = (const float*)d_in[9];
    const float* bt   = (const float*)d_in[10];
    const float* w1   = (const float*)d_in[11];
    const float* b1   = (const float*)d_in[12];
    const float* w2   = (const float*)d_in[13];
    const float* b2   = (const float*)d_in[14];
    const float* ln1g = (const float*)d_in[15];
    const float* ln1b = (const float*)d_in[16];
    const float* ln2g = (const float*)d_in[17];
    const float* ln2b = (const float*)d_in[18];
    float* out = (float*)d_out;

    float *hb, *o1, *bqkv;
    fp16 *xnh, *xnl, *qkvh, *qkvl, *cxh, *cxl, *f1h, *f1l;
    fp16 *wqkvp, *wop, *w1p, *w2p;
    cudaGetSymbolAddress((void**)&hb,   g_h);
    cudaGetSymbolAddress((void**)&o1,   g_out1);
    cudaGetSymbolAddress((void**)&bqkv, g_bqkv);
    cudaGetSymbolAddress((void**)&xnh,  g_xn_h);  cudaGetSymbolAddress((void**)&xnl, g_xn_l);
    cudaGetSymbolAddress((void**)&qkvh, g_qkv_h); cudaGetSymbolAddress((void**)&qkvl, g_qkv_l);
    cudaGetSymbolAddress((void**)&cxh,  g_ctx_h); cudaGetSymbolAddress((void**)&cxl, g_ctx_l);
    cudaGetSymbolAddress((void**)&f1h,  g_f1_h);  cudaGetSymbolAddress((void**)&f1l, g_f1_l);
    cudaGetSymbolAddress((void**)&wqkvp, g_wqkvT);
    cudaGetSymbolAddress((void**)&wop,  g_woT);
    cudaGetSymbolAddress((void**)&w1p,  g_w1T);
    cudaGetSymbolAddress((void**)&w2p,  g_w2T);

    cudaFuncSetAttribute(attn_mma_kernel, cudaFuncAttributeMaxDynamicSharedMemorySize, ATTN_SMEM);
    cudaFuncSetAttribute(gemm_mma_kernel, cudaFuncAttributeMaxDynamicSharedMemorySize, GEMM_SMEM);

    dim3 gQKV(D3 / 128, M_ / 128);
    dim3 gD(D_ / 128, M_ / 128);
    dim3 gF(F_ / 128, M_ / 128);
    dim3 gAttn(S_ / QT, H_, B_);

    addpe_kernel<<<(M_ * D_) / 256, 256>>>(x, pe, hb);
    packb_kernel<<<dim3(D_ / 256, L_), 256>>>(bq, bk, bv, bqkv);
    wtransqkv_kernel<<<dim3(32, 32, 3 * L_), 256>>>(wq, wk, wv, wqkvp);
    wtrans_kernel<<<dim3(32, 32, L_), 256>>>(wo, wop, D_, D_, (size_t)D_ * D_);
    wtrans_kernel<<<dim3(F_ / 32, D_ / 32, L_), 256>>>(w1, w1p, D_, F_, (size_t)D_ * F_);
    wtrans_kernel<<<dim3(D_ / 32, F_ / 32, L_), 256>>>(w2, w2p, F_, D_, (size_t)F_ * D_);

    for (int l = 0; l < L_; l++) {
        size_t oQKV = (size_t)l * D3 * D_;
        size_t oDD  = (size_t)l * D_ * D_;
        size_t oDF  = (size_t)l * D_ * F_;
        size_t oD   = (size_t)l * D_;
        size_t oF   = (size_t)l * F_;

        ln_kernel<<<M_, 256>>>(hb, ln1g + oD, ln1b + oD, xnh, xnl);
        gemm_mma_kernel<<<gQKV, 256, GEMM_SMEM>>>(xnh, xnl, wqkvp + oQKV,
            bqkv + (size_t)l * D3, nullptr, nullptr, nullptr, qkvh, qkvl, D3, D_, 0);

        attn_mma_kernel<<<gAttn, 256, ATTN_SMEM>>>(qkvh, qkvl,
            bt + (size_t)l * (2 * P_ - 1) * H_, cxh, cxl);

        gemm_mma_kernel<<<gD, 256, GEMM_SMEM>>>(cxh, cxl, wop + oDD,
            bo + oD, hb, nullptr, o1, nullptr, nullptr, D_, D_, 0);

        ln_kernel<<<M_, 256>>>(o1, ln2g + oD, ln2b + oD, xnh, xnl);
        gemm_mma_kernel<<<gF, 256, GEMM_SMEM>>>(xnh, xnl, w1p + oDF,
            b1 + oF, nullptr, nullptr, nullptr, f1h, f1l, F_, D_, 1);
        float* dst = (l == L_ - 1) ? out : hb;
        gemm_mma_kernel<<<gD, 256, GEMM_SMEM>>>(f1h, f1l, w2p + oDF,
            b2 + oD, o1, hb, dst, nullptr, nullptr, D_, F_, 0);
    }
}

// round 13
// speedup vs baseline: 4.6454x; 1.5318x over previous
#include <cuda_runtime.h>
#include <cuda_fp16.h>
#include <math.h>
#include <cstdint>

using fp16 = __half;

static constexpr int L_ = 6, D_ = 1024, H_ = 16, F_ = 4096, S_ = 512, B_ = 16, P_ = 512;
static constexpr int DH_ = D_ / H_;
static constexpr int M_ = B_ * S_;
static constexpr int D3 = 3 * D_;

// ---------------- scratch ----------------------------------------------------
__device__ __align__(16) float g_h[(size_t)M_ * D_];
__device__ __align__(16) float g_out1[(size_t)M_ * D_];

__device__ __align__(16) fp16 g_xn[(size_t)M_ * D_];
__device__ __align__(16) fp16 g_qkv[(size_t)M_ * D3];
__device__ __align__(16) fp16 g_ctx[(size_t)M_ * D_];
__device__ __align__(16) fp16 g_f1[(size_t)M_ * F_];

__device__ __align__(16) fp16 g_wqkvT[(size_t)L_ * D3 * D_];
__device__ __align__(16) fp16 g_woT[(size_t)L_ * D_ * D_];
__device__ __align__(16) fp16 g_w1T[(size_t)L_ * D_ * F_];
__device__ __align__(16) fp16 g_w2T[(size_t)L_ * F_ * D_];
__device__ __align__(16) float g_bqkv[(size_t)L_ * D3];

// ---------------- PTX helpers -------------------------------------------------
__device__ __forceinline__ uint32_t smem_u32(const void* p) {
    uint32_t a;
    asm("{ .reg .u64 t; cvta.to.shared.u64 t, %1; cvt.u32.u64 %0, t; }" : "=r"(a) : "l"(p));
    return a;
}
__device__ __forceinline__ void ldsm4(uint32_t* r, uint32_t addr) {
    asm volatile("ldmatrix.sync.aligned.m8n8.x4.shared.b16 {%0,%1,%2,%3}, [%4];"
                 : "=r"(r[0]), "=r"(r[1]), "=r"(r[2]), "=r"(r[3]) : "r"(addr));
}
__device__ __forceinline__ void ldsm4t(uint32_t* r, uint32_t addr) {
    asm volatile("ldmatrix.sync.aligned.m8n8.x4.trans.shared.b16 {%0,%1,%2,%3}, [%4];"
                 : "=r"(r[0]), "=r"(r[1]), "=r"(r[2]), "=r"(r[3]) : "r"(addr));
}
__device__ __forceinline__ void mma16816h(float* d, const uint32_t* a, uint32_t b0, uint32_t b1) {
    asm volatile("mma.sync.aligned.m16n8k16.row.col.f32.f16.f16.f32 "
                 "{%0,%1,%2,%3}, {%4,%5,%6,%7}, {%8,%9}, {%0,%1,%2,%3};"
                 : "+f"(d[0]), "+f"(d[1]), "+f"(d[2]), "+f"(d[3])
                 : "r"(a[0]), "r"(a[1]), "r"(a[2]), "r"(a[3]), "r"(b0), "r"(b1));
}
#define CPA(dst, src)  asm volatile("cp.async.cg.shared.global [%0], [%1], 16;" :: "r"(dst), "l"(src))
#define CPA_COMMIT()   asm volatile("cp.async.commit_group;" ::: "memory")
#define CPA_WAIT1()    asm volatile("cp.async.wait_group 1;" ::: "memory")
#define CPA_WAIT0()    asm volatile("cp.async.wait_group 0;" ::: "memory")

__device__ __forceinline__ uint32_t swz(uint32_t off)   { return off ^ ((off >> 3) & 0x70); }
__device__ __forceinline__ uint32_t swz64(uint32_t off) { return off ^ ((off >> 3) & 0x30); }
__device__ __forceinline__ uint32_t smx(uint32_t r, uint32_t c)   { return r + (c ^ ((r >> 3) & 0x70)); }
__device__ __forceinline__ uint32_t smx64(uint32_t r, uint32_t c) { return r + (c ^ ((r >> 3) & 0x30)); }

// ---------------- h = x + pe -------------------------------------------------
__global__ __launch_bounds__(256) void addpe_kernel(const float* __restrict__ x,
                                                    const float* __restrict__ pe,
                                                    float* __restrict__ h) {
    int i = blockIdx.x * 256 + threadIdx.x;
    h[i] = x[i] + pe[i & (S_ * D_ - 1)];
}

// ---------------- pack qkv bias ----------------------------------------------
__global__ __launch_bounds__(256) void packb_kernel(const float* __restrict__ bq,
                                                    const float* __restrict__ bk,
                                                    const float* __restrict__ bv,
                                                    float* __restrict__ o) {
    int l = blockIdx.y;
    int i = blockIdx.x * 256 + threadIdx.x;
    o[(size_t)l * D3 + i]          = bq[l * D_ + i];
    o[(size_t)l * D3 + D_ + i]     = bk[l * D_ + i];
    o[(size_t)l * D3 + 2 * D_ + i] = bv[l * D_ + i];
}

// ---------------- weight transpose: W[K,N] -> T[N,K] fp16 --------------------
__global__ __launch_bounds__(256) void wtrans_kernel(const float* __restrict__ W,
                                                     fp16* __restrict__ T,
                                                     int K, int N, size_t out_ls) {
    __shared__ float t[32][33];
    size_t inoff  = (size_t)blockIdx.z * K * N;
    size_t outoff = (size_t)blockIdx.z * out_ls;
    int k0 = blockIdx.y * 32, n0 = blockIdx.x * 32;
    int tx = threadIdx.x & 31, ty = threadIdx.x >> 5;
#pragma unroll
    for (int i = 0; i < 32; i += 8)
        t[ty + i][tx] = W[inoff + (size_t)(k0 + ty + i) * N + n0 + tx];
    __syncthreads();
#pragma unroll
    for (int i = 0; i < 32; i += 8)
        T[outoff + (size_t)(n0 + ty + i) * K + k0 + tx] = __float2half_rn(t[tx][ty + i]);
}

// merged q/k/v transpose -> fused [D3,K] fp16
__global__ __launch_bounds__(256) void wtransqkv_kernel(const float* __restrict__ wq,
                                                        const float* __restrict__ wk,
                                                        const float* __restrict__ wv,
                                                        fp16* __restrict__ T) {
    __shared__ float t[32][33];
    int z = blockIdx.z;
    int l = z / 3, which = z - l * 3;
    const float* W = (which == 0) ? wq : (which == 1) ? wk : wv;
    size_t inoff  = (size_t)l * D_ * D_;
    size_t outoff = (size_t)l * D3 * D_ + (size_t)which * D_ * D_;
    int k0 = blockIdx.y * 32, n0 = blockIdx.x * 32;
    int tx = threadIdx.x & 31, ty = threadIdx.x >> 5;
#pragma unroll
    for (int i = 0; i < 32; i += 8)
        t[ty + i][tx] = W[inoff + (size_t)(k0 + ty + i) * D_ + n0 + tx];
    __syncthreads();
#pragma unroll
    for (int i = 0; i < 32; i += 8)
        T[outoff + (size_t)(n0 + ty + i) * D_ + k0 + tx] = __float2half_rn(t[tx][ty + i]);
}

// ---------------- LayerNorm: fp32 in -> fp16 out ------------------------------
__global__ __launch_bounds__(256) void ln_kernel(const float* __restrict__ x,
                                                 const float* __restrict__ g,
                                                 const float* __restrict__ b,
                                                 fp16* __restrict__ y) {
    int row = blockIdx.x, tid = threadIdx.x;
    float4 f = *(const float4*)(x + (size_t)row * D_ + tid * 4);
    float s  = f.x + f.y + f.z + f.w;
    float ss = f.x*f.x + f.y*f.y + f.z*f.z + f.w*f.w;
#pragma unroll
    for (int o = 16; o > 0; o >>= 1) {
        s  += __shfl_xor_sync(0xffffffffu, s, o);
        ss += __shfl_xor_sync(0xffffffffu, ss, o);
    }
    __shared__ float rs[8], rss[8];
    if ((tid & 31) == 0) { rs[tid >> 5] = s; rss[tid >> 5] = ss; }
    __syncthreads();
    float ts = 0.f, tss = 0.f;
#pragma unroll
    for (int i = 0; i < 8; i++) { ts += rs[i]; tss += rss[i]; }
    float mean = ts * (1.0f / D_);
    float var  = tss * (1.0f / D_) - mean * mean;
    float r    = rsqrtf(var + 1e-6f);
    float4 g4 = *(const float4*)(g + tid * 4);
    float4 b4 = *(const float4*)(b + tid * 4);
    float o[4];
    o[0]=(f.x-mean)*r*g4.x+b4.x; o[1]=(f.y-mean)*r*g4.y+b4.y;
    o[2]=(f.z-mean)*r*g4.z+b4.z; o[3]=(f.w-mean)*r*g4.w+b4.w;
    size_t base = (size_t)row * D_ + tid * 4;
#pragma unroll
    for (int j = 0; j < 4; j += 2)
        *(__half2*)(y + base + j) = __halves2half2(__float2half_rn(o[j]), __float2half_rn(o[j+1]));
}

// ---------------- fp16 mma.sync GEMM 128x128, Kc=32, SW64, x3, occ2 ----------
// C = act(A@B^T + bias) + r1 + r2
static constexpr int TILE32 = 128 * 32 * 2;     // 8 KB
static constexpr int S_A = 0, S_B = TILE32;
static constexpr int STAGEB = 2 * TILE32;       // 16 KB
static constexpr int GEMM_SMEM = 3 * STAGEB;    // 48 KB -> 2 CTAs/SM (reg-bound)

__device__ __forceinline__ void tile_cpa32(const fp16* __restrict__ g,
                                           int row0, int stride, int k0,
                                           uint32_t sdst, int tid) {
#pragma unroll
    for (int i = 0; i < 2; i++) {
        int idx = i * 256 + tid;
        int r = idx >> 2, c = idx & 3;
        CPA(sdst + swz64(r * 64 + c * 16), g + (size_t)(row0 + r) * stride + k0 + c * 8);
    }
}

__global__ __launch_bounds__(256, 2) void gemm_mma_kernel(
    const fp16* __restrict__ A, const fp16* __restrict__ Bm,
    const float* __restrict__ bias, const float* __restrict__ r1,
    const float* __restrict__ r2, float* __restrict__ C,
    fp16* __restrict__ Ch, int NN, int KK, int act) {
    extern __shared__ char smem[];
    const uint32_t sb = smem_u32(smem);
    const int tid = threadIdx.x;
    const int wid = tid >> 5, lane = tid & 31;
    const int wm = wid >> 2, wn = wid & 3;
    const int rowBase = blockIdx.y * 128, colBase = blockIdx.x * 128;

    float acc[4][4][4];
#pragma unroll
    for (int i = 0; i < 4; i++)
#pragma unroll
        for (int j = 0; j < 4; j++)
#pragma unroll
            for (int q = 0; q < 4; q++) acc[i][j][q] = 0.f;

    const uint32_t a_row = (uint32_t)((wm * 64 + (lane & 15)) * 64);
    const uint32_t a_col = (uint32_t)((lane >> 4) * 16);
    const uint32_t b_row0 = (uint32_t)((wn * 32 + (lane & 7) + ((lane >> 4) << 3)) * 64);
    const uint32_t b_col = (uint32_t)(((lane >> 3) & 1) * 16);

    const int nc = KK / 32;
    tile_cpa32(A,  rowBase, KK, 0, sb + S_A, tid);
    tile_cpa32(Bm, colBase, KK, 0, sb + S_B, tid);
    CPA_COMMIT();
    {
        uint32_t st = sb + STAGEB;
        tile_cpa32(A,  rowBase, KK, 32, st + S_A, tid);
        tile_cpa32(Bm, colBase, KK, 32, st + S_B, tid);
    }
    CPA_COMMIT();

    for (int c = 0; c < nc; c++) {
        if (c + 1 < nc) CPA_WAIT1(); else CPA_WAIT0();
        __syncthreads();
        if (c + 2 < nc) {
            uint32_t st = sb + ((c + 2) % 3) * STAGEB;
            int k0 = (c + 2) * 32;
            tile_cpa32(A,  rowBase, KK, k0, st + S_A, tid);
            tile_cpa32(Bm, colBase, KK, k0, st + S_B, tid);
            CPA_COMMIT();
        }
        uint32_t st = sb + (c % 3) * STAGEB;

#pragma unroll
        for (int ks = 0; ks < 2; ks++) {
            const uint32_t kb = ks * 32;
            uint32_t bh[2][4];
#pragma unroll
            for (int g = 0; g < 2; g++) {
                uint32_t roff = b_row0 + (uint32_t)(g * 16 * 64);
                ldsm4(bh[g], st + S_B + smx64(roff, kb + b_col));
            }
#pragma unroll
            for (int mi = 0; mi < 4; mi++) {
                uint32_t roff = a_row + (uint32_t)(mi * 16 * 64);
                uint32_t af[4];
                ldsm4(af, st + S_A + smx64(roff, kb + a_col));
#pragma unroll
                for (int nj = 0; nj < 4; nj++) {
                    int g = nj >> 1, o = (nj & 1) * 2;
                    mma16816h(acc[mi][nj], af, bh[g][o], bh[g][o + 1]);
                }
            }
        }
    }

    const int tq = lane >> 2, tr = lane & 3;
#pragma unroll
    for (int mi = 0; mi < 4; mi++) {
#pragma unroll
        for (int nj = 0; nj < 4; nj++) {
            int n = colBase + wn * 32 + nj * 8 + tr * 2;
            float2 bb = *(const float2*)(bias + n);
#pragma unroll
            for (int half = 0; half < 2; half++) {
                int m = rowBase + wm * 64 + mi * 16 + tq + half * 8;
                size_t base = (size_t)m * NN + n;
                float v0 = acc[mi][nj][half * 2 + 0] + bb.x;
                float v1 = acc[mi][nj][half * 2 + 1] + bb.y;
                if (act == 1) { v0 = v0 * normcdff(v0); v1 = v1 * normcdff(v1); }
                if (r1) { float2 q = *(const float2*)(r1 + base); v0 += q.x; v1 += q.y; }
                if (r2) { float2 q = *(const float2*)(r2 + base); v0 += q.x; v1 += q.y; }
                if (C) { float2 ov = {v0, v1}; *(float2*)(C + base) = ov; }
                if (Ch)
                    *(__half2*)(Ch + base) = __halves2half2(__float2half_rn(v0), __float2half_rn(v1));
            }
        }
    }
}

// ---------------- tensor-core attention (single-plane fp16) ------------------
static constexpr int QT = 32;
static constexpr int SCS2 = 520;
static constexpr int AO_Q  = 0;                 // 4096
static constexpr int AO_KV = 4096;              // 2 stages x 8192
static constexpr int AO_SC = 20480;             // 66560
static constexpr int AO_AW = 87040;             // 33280
static constexpr int ATTN_SMEM = 120320;

__device__ __forceinline__ void tile64_cpa(const fp16* __restrict__ g,
                                           int row0, int stride, uint32_t sdst, int tid) {
#pragma unroll
    for (int i = 0; i < 2; i++) {
        int idx = i * 256 + tid;
        int r = idx >> 3, c = idx & 7;
        CPA(sdst + swz(r * 128 + c * 16), g + (size_t)(row0 + r) * stride + c * 8);
    }
}

__global__ __launch_bounds__(256, 1) void attn_mma_kernel(
    const fp16* __restrict__ qkv, const float* __restrict__ bias,
    fp16* __restrict__ Ctx) {
    extern __shared__ char smem[];
    const uint32_t sb = smem_u32(smem);
    const int tid = threadIdx.x;
    const int wid = tid >> 5, lane = tid & 31;
    const int wm = wid >> 2, wn = wid & 3;
    const int q0 = blockIdx.x * QT, h = blockIdx.y, b = blockIdx.z;
    const size_t base3 = (size_t)(b * S_) * D3 + h * DH_;
    const fp16* Q = qkv + base3;
    const fp16* K = qkv + base3 + D_;
    const fp16* V = qkv + base3 + 2 * D_;
    const int tq = lane >> 2, tr = lane & 3;

    {
        int r = tid >> 3, c = tid & 7;
        CPA(sb + AO_Q + swz(r * 128 + c * 16), Q + (size_t)(q0 + r) * D3 + c * 8);
    }
    tile64_cpa(K, 0, D3, sb + AO_KV, tid);
    CPA_COMMIT();
    CPA_WAIT0();
    __syncthreads();

    uint32_t qf[4][4];
    {
        uint32_t arow = (uint32_t)((wm * 16 + (lane & 15)) * 128);
        uint32_t acol = (uint32_t)((lane >> 4) * 16);
#pragma unroll
        for (int ks = 0; ks < 4; ks++)
            ldsm4(qf[ks], sb + AO_Q + smx(arow, ks * 32 + acol));
    }

    const uint32_t b_row = (uint32_t)((wn * 16 + (lane & 7) + ((lane >> 4) << 3)) * 128);
    const uint32_t b_col = (uint32_t)(((lane >> 3) & 1) * 16);
    for (int c = 0; c < 8; c++) {
        if (c < 7) {
            uint32_t st = sb + AO_KV + ((c + 1) & 1) * 8192;
            tile64_cpa(K, (c + 1) * 64, D3, st, tid);
            CPA_COMMIT();
            CPA_WAIT1();
        } else {
            CPA_WAIT0();
        }
        __syncthreads();
        uint32_t st = sb + AO_KV + (c & 1) * 8192;

        float acc[2][4] = {};
#pragma unroll
        for (int ks = 0; ks < 4; ks++) {
            uint32_t kh4[4];
            ldsm4(kh4, st + smx(b_row, ks * 32 + b_col));
#pragma unroll
            for (int nj = 0; nj < 2; nj++)
                mma16816h(acc[nj], qf[ks], kh4[nj * 2], kh4[nj * 2 + 1]);
        }
        float* sc = (float*)(smem + AO_SC);
#pragma unroll
        for (int nj = 0; nj < 2; nj++) {
            int kg = c * 64 + wn * 16 + nj * 8 + tr * 2;
#pragma unroll
            for (int half = 0; half < 2; half++) {
                int m = wm * 16 + tq + half * 8;
                int rel = (q0 + m) - kg + (P_ - 1);
                sc[m * SCS2 + kg]     = acc[nj][half*2+0] * 0.125f + __ldg(&bias[rel * H_ + h]);
                sc[m * SCS2 + kg + 1] = acc[nj][half*2+1] * 0.125f + __ldg(&bias[(rel - 1) * H_ + h]);
            }
        }
        __syncthreads();
    }

    tile64_cpa(V, 0, D3, sb + AO_KV, tid);
    CPA_COMMIT();

    {
        float* sc = (float*)(smem + AO_SC);
        fp16* aw = (fp16*)(smem + AO_AW);
#pragma unroll
        for (int rr = 0; rr < 4; rr++) {
            int r = wid * 4 + rr;
            float* row = sc + r * SCS2;
            float mx = -1e30f;
            for (int cc = lane; cc < S_; cc += 32) mx = fmaxf(mx, row[cc]);
#pragma unroll
            for (int o = 16; o > 0; o >>= 1) mx = fmaxf(mx, __shfl_xor_sync(0xffffffffu, mx, o));
            float sum = 0.f;
            for (int cc = lane; cc < S_; cc += 32) {
                float e = expf(row[cc] - mx);
                row[cc] = e;
                sum += e;
            }
#pragma unroll
            for (int o = 16; o > 0; o >>= 1) sum += __shfl_xor_sync(0xffffffffu, sum, o);
            float inv = 1.0f / sum;
            for (int cc = lane; cc < S_; cc += 32)
                aw[r * SCS2 + cc] = __float2half_rn(row[cc] * inv);
        }
    }
    __syncthreads();

    float cacc[2][4] = {};
    const uint32_t aw_row = (uint32_t)((wm * 16 + (lane & 15)) * (SCS2 * 2));
    const uint32_t v_row = (uint32_t)(((lane & 7) + ((lane >> 3) & 1) * 8) * 128);
    const uint32_t v_col = (uint32_t)(wn * 32 + (lane >> 4) * 16);
    for (int c = 0; c < 8; c++) {
        if (c < 7) {
            uint32_t st = sb + AO_KV + ((c + 1) & 1) * 8192;
            tile64_cpa(V, (c + 1) * 64, D3, st, tid);
            CPA_COMMIT();
            CPA_WAIT1();
        } else {
            CPA_WAIT0();
        }
        __syncthreads();
        uint32_t st = sb + AO_KV + (c & 1) * 8192;

#pragma unroll
        for (int ks = 0; ks < 4; ks++) {
            uint32_t awoff = aw_row + (uint32_t)((c * 64 + ks * 16 + (lane >> 4) * 8) * 2);
            uint32_t ah4[4];
            ldsm4(ah4, sb + AO_AW + awoff);
            uint32_t vh4[4];
            ldsm4t(vh4, st + smx(v_row + (uint32_t)(ks * 16 * 128), v_col));
#pragma unroll
            for (int nj = 0; nj < 2; nj++)
                mma16816h(cacc[nj], ah4, vh4[nj * 2], vh4[nj * 2 + 1]);
        }
        __syncthreads();
    }

#pragma unroll
    for (int nj = 0; nj < 2; nj++) {
        int n = wn * 16 + nj * 8 + tr * 2;
#pragma unroll
        for (int half = 0; half < 2; half++) {
            int m = wm * 16 + tq + half * 8;
            size_t gidx = (size_t)(b * S_ + q0 + m) * D_ + h * DH_ + n;
            *(__half2*)(Ctx + gidx) = __halves2half2(
                __float2half_rn(cacc[nj][half*2+0]), __float2half_rn(cacc[nj][half*2+1]));
        }
    }
}

// ---------------- launch ----------------------------------------------------
extern "C" void kernel_launch(void* const* d_in, const int* in_sizes, int n_in,
                              void* d_out, int out_size) {
    (void)in_sizes; (void)n_in; (void)out_size;
    const float* x    = (const float*)d_in[0];
    const float* pe   = (const float*)d_in[1];
    const float* wq   = (const float*)d_in[2];
    const float* bq   = (const float*)d_in[3];
    const float* wk   = (const float*)d_in[4];
    const float* bk   = (const float*)d_in[5];
    const float* wv   = (const float*)d_in[6];
    const float* bv   = (const float*)d_in[7];
    const float* wo   = (const float*)d_in[8];
    const float* bo   = (const float*)d_in[9];
    const float* bt   = (const float*)d_in[10];
    const float* w1   = (const float*)d_in[11];
    const float* b1   = (const float*)d_in[12];
    const float* w2   = (const float*)d_in[13];
    const float* b2   = (const float*)d_in[14];
    const float* ln1g = (const float*)d_in[15];
    const float* ln1b = (const float*)d_in[16];
    const float* ln2g = (const float*)d_in[17];
    const float* ln2b = (const float*)d_in[18];
    float* out = (float*)d_out;

    float *hb, *o1, *bqkv;
    fp16 *xn, *qkv, *cx, *f1, *wqkvp, *wop, *w1p, *w2p;
    cudaGetSymbolAddress((void**)&hb,   g_h);
    cudaGetSymbolAddress((void**)&o1,   g_out1);
    cudaGetSymbolAddress((void**)&bqkv, g_bqkv);
    cudaGetSymbolAddress((void**)&xn,   g_xn);
    cudaGetSymbolAddress((void**)&qkv,  g_qkv);
    cudaGetSymbolAddress((void**)&cx,   g_ctx);
    cudaGetSymbolAddress((void**)&f1,   g_f1);
    cudaGetSymbolAddress((void**)&wqkvp, g_wqkvT);
    cudaGetSymbolAddress((void**)&wop,  g_woT);
    cudaGetSymbolAddress((void**)&w1p,  g_w1T);
    cudaGetSymbolAddress((void**)&w2p,  g_w2T);

    cudaFuncSetAttribute(attn_mma_kernel, cudaFuncAttributeMaxDynamicSharedMemorySize, ATTN_SMEM);
    cudaFuncSetAttribute(gemm_mma_kernel, cudaFuncAttributeMaxDynamicSharedMemorySize, GEMM_SMEM);

    dim3 gQKV(D3 / 128, M_ / 128);
    dim3 gD(D_ / 128, M_ / 128);
    dim3 gF(F_ / 128, M_ / 128);
    dim3 gAttn(S_ / QT, H_, B_);

    addpe_kernel<<<(M_ * D_) / 256, 256>>>(x, pe, hb);
    packb_kernel<<<dim3(D_ / 256, L_), 256>>>(bq, bk, bv, bqkv);
    wtransqkv_kernel<<<dim3(32, 32, 3 * L_), 256>>>(wq, wk, wv, wqkvp);
    wtrans_kernel<<<dim3(32, 32, L_), 256>>>(wo, wop, D_, D_, (size_t)D_ * D_);
    wtrans_kernel<<<dim3(F_ / 32, D_ / 32, L_), 256>>>(w1, w1p, D_, F_, (size_t)D_ * F_);
    wtrans_kernel<<<dim3(D_ / 32, F_ / 32, L_), 256>>>(w2, w2p, F_, D_, (size_t)F_ * D_);

    for (int l = 0; l < L_; l++) {
        size_t oQKV = (size_t)l * D3 * D_;
        size_t oDD  = (size_t)l * D_ * D_;
        size_t oDF  = (size_t)l * D_ * F_;
        size_t oD   = (size_t)l * D_;
        size_t oF   = (size_t)l * F_;

        ln_kernel<<<M_, 256>>>(hb, ln1g + oD, ln1b + oD, xn);
        gemm_mma_kernel<<<gQKV, 256, GEMM_SMEM>>>(xn, wqkvp + oQKV,
            bqkv + (size_t)l * D3, nullptr, nullptr, nullptr, qkv, D3, D_, 0);

        attn_mma_kernel<<<gAttn, 256, ATTN_SMEM>>>(qkv,
            bt + (size_t)l * (2 * P_ - 1) * H_, cx);

        gemm_mma_kernel<<<gD, 256, GEMM_SMEM>>>(cx, wop + oDD,
            bo + oD, hb, nullptr, o1, nullptr, D_, D_, 0);

        ln_kernel<<<M_, 256>>>(o1, ln2g + oD, ln2b + oD, xn);
        gemm_mma_kernel<<<gF, 256, GEMM_SMEM>>>(xn, w1p + oDF,
            b1 + oF, nullptr, nullptr, nullptr, f1, F_, D_, 1);
        float* dst = (l == L_ - 1) ? out : hb;
        gemm_mma_kernel<<<gD, 256, GEMM_SMEM>>>(f1, w2p + oDF,
            b2 + oD, o1, hb, dst, nullptr, D_, F_, 0);
    }
}

// round 14
// speedup vs baseline: 4.7802x; 1.0290x over previous
#include <cuda_runtime.h>
#include <cuda_fp16.h>
#include <math.h>
#include <cstdint>

using fp16 = __half;

static constexpr int L_ = 6, D_ = 1024, H_ = 16, F_ = 4096, S_ = 512, B_ = 16, P_ = 512;
static constexpr int DH_ = D_ / H_;
static constexpr int M_ = B_ * S_;
static constexpr int D3 = 3 * D_;

// ---------------- scratch ----------------------------------------------------
__device__ __align__(16) float g_h[(size_t)M_ * D_];
__device__ __align__(16) float g_out1[(size_t)M_ * D_];

__device__ __align__(16) fp16 g_xn[(size_t)M_ * D_];
__device__ __align__(16) fp16 g_qkv[(size_t)M_ * D3];
__device__ __align__(16) fp16 g_ctx[(size_t)M_ * D_];
__device__ __align__(16) fp16 g_f1[(size_t)M_ * F_];

__device__ __align__(16) fp16 g_wqkvT[(size_t)L_ * D3 * D_];
__device__ __align__(16) fp16 g_woT[(size_t)L_ * D_ * D_];
__device__ __align__(16) fp16 g_w1T[(size_t)L_ * D_ * F_];
__device__ __align__(16) fp16 g_w2T[(size_t)L_ * F_ * D_];
__device__ __align__(16) float g_bqkv[(size_t)L_ * D3];

// ---------------- PTX helpers -------------------------------------------------
__device__ __forceinline__ uint32_t smem_u32(const void* p) {
    uint32_t a;
    asm("{ .reg .u64 t; cvta.to.shared.u64 t, %1; cvt.u32.u64 %0, t; }" : "=r"(a) : "l"(p));
    return a;
}
__device__ __forceinline__ void ldsm4(uint32_t* r, uint32_t addr) {
    asm volatile("ldmatrix.sync.aligned.m8n8.x4.shared.b16 {%0,%1,%2,%3}, [%4];"
                 : "=r"(r[0]), "=r"(r[1]), "=r"(r[2]), "=r"(r[3]) : "r"(addr));
}
__device__ __forceinline__ void ldsm4t(uint32_t* r, uint32_t addr) {
    asm volatile("ldmatrix.sync.aligned.m8n8.x4.trans.shared.b16 {%0,%1,%2,%3}, [%4];"
                 : "=r"(r[0]), "=r"(r[1]), "=r"(r[2]), "=r"(r[3]) : "r"(addr));
}
__device__ __forceinline__ void mma16816h(float* d, const uint32_t* a, uint32_t b0, uint32_t b1) {
    asm volatile("mma.sync.aligned.m16n8k16.row.col.f32.f16.f16.f32 "
                 "{%0,%1,%2,%3}, {%4,%5,%6,%7}, {%8,%9}, {%0,%1,%2,%3};"
                 : "+f"(d[0]), "+f"(d[1]), "+f"(d[2]), "+f"(d[3])
                 : "r"(a[0]), "r"(a[1]), "r"(a[2]), "r"(a[3]), "r"(b0), "r"(b1));
}
#define CPA(dst, src)  asm volatile("cp.async.cg.shared.global [%0], [%1], 16;" :: "r"(dst), "l"(src))
#define CPA_COMMIT()   asm volatile("cp.async.commit_group;" ::: "memory")
#define CPA_WAIT1()    asm volatile("cp.async.wait_group 1;" ::: "memory")
#define CPA_WAIT0()    asm volatile("cp.async.wait_group 0;" ::: "memory")

__device__ __forceinline__ uint32_t swz(uint32_t off) { return off ^ ((off >> 3) & 0x70); }
__device__ __forceinline__ uint32_t smx(uint32_t r, uint32_t c) { return r + (c ^ ((r >> 3) & 0x70)); }

// ---------------- h = x + pe -------------------------------------------------
__global__ __launch_bounds__(256) void addpe_kernel(const float* __restrict__ x,
                                                    const float* __restrict__ pe,
                                                    float* __restrict__ h) {
    int i = blockIdx.x * 256 + threadIdx.x;
    h[i] = x[i] + pe[i & (S_ * D_ - 1)];
}

// ---------------- pack qkv bias ----------------------------------------------
__global__ __launch_bounds__(256) void packb_kernel(const float* __restrict__ bq,
                                                    const float* __restrict__ bk,
                                                    const float* __restrict__ bv,
                                                    float* __restrict__ o) {
    int l = blockIdx.y;
    int i = blockIdx.x * 256 + threadIdx.x;
    o[(size_t)l * D3 + i]          = bq[l * D_ + i];
    o[(size_t)l * D3 + D_ + i]     = bk[l * D_ + i];
    o[(size_t)l * D3 + 2 * D_ + i] = bv[l * D_ + i];
}

// ---------------- weight transpose: W[K,N] -> T[N,K] fp16 --------------------
__global__ __launch_bounds__(256) void wtrans_kernel(const float* __restrict__ W,
                                                     fp16* __restrict__ T,
                                                     int K, int N, size_t out_ls) {
    __shared__ float t[32][33];
    size_t inoff  = (size_t)blockIdx.z * K * N;
    size_t outoff = (size_t)blockIdx.z * out_ls;
    int k0 = blockIdx.y * 32, n0 = blockIdx.x * 32;
    int tx = threadIdx.x & 31, ty = threadIdx.x >> 5;
#pragma unroll
    for (int i = 0; i < 32; i += 8)
        t[ty + i][tx] = W[inoff + (size_t)(k0 + ty + i) * N + n0 + tx];
    __syncthreads();
#pragma unroll
    for (int i = 0; i < 32; i += 8)
        T[outoff + (size_t)(n0 + ty + i) * K + k0 + tx] = __float2half_rn(t[tx][ty + i]);
}

// merged q/k/v transpose -> fused [D3,K] fp16
__global__ __launch_bounds__(256) void wtransqkv_kernel(const float* __restrict__ wq,
                                                        const float* __restrict__ wk,
                                                        const float* __restrict__ wv,
                                                        fp16* __restrict__ T) {
    __shared__ float t[32][33];
    int z = blockIdx.z;
    int l = z / 3, which = z - l * 3;
    const float* W = (which == 0) ? wq : (which == 1) ? wk : wv;
    size_t inoff  = (size_t)l * D_ * D_;
    size_t outoff = (size_t)l * D3 * D_ + (size_t)which * D_ * D_;
    int k0 = blockIdx.y * 32, n0 = blockIdx.x * 32;
    int tx = threadIdx.x & 31, ty = threadIdx.x >> 5;
#pragma unroll
    for (int i = 0; i < 32; i += 8)
        t[ty + i][tx] = W[inoff + (size_t)(k0 + ty + i) * D_ + n0 + tx];
    __syncthreads();
#pragma unroll
    for (int i = 0; i < 32; i += 8)
        T[outoff + (size_t)(n0 + ty + i) * D_ + k0 + tx] = __float2half_rn(t[tx][ty + i]);
}

// ---------------- LayerNorm: fp32 in -> fp16 out ------------------------------
__global__ __launch_bounds__(256) void ln_kernel(const float* __restrict__ x,
                                                 const float* __restrict__ g,
                                                 const float* __restrict__ b,
                                                 fp16* __restrict__ y) {
    int row = blockIdx.x, tid = threadIdx.x;
    float4 f = *(const float4*)(x + (size_t)row * D_ + tid * 4);
    float s  = f.x + f.y + f.z + f.w;
    float ss = f.x*f.x + f.y*f.y + f.z*f.z + f.w*f.w;
#pragma unroll
    for (int o = 16; o > 0; o >>= 1) {
        s  += __shfl_xor_sync(0xffffffffu, s, o);
        ss += __shfl_xor_sync(0xffffffffu, ss, o);
    }
    __shared__ float rs[8], rss[8];
    if ((tid & 31) == 0) { rs[tid >> 5] = s; rss[tid >> 5] = ss; }
    __syncthreads();
    float ts = 0.f, tss = 0.f;
#pragma unroll
    for (int i = 0; i < 8; i++) { ts += rs[i]; tss += rss[i]; }
    float mean = ts * (1.0f / D_);
    float var  = tss * (1.0f / D_) - mean * mean;
    float r    = rsqrtf(var + 1e-6f);
    float4 g4 = *(const float4*)(g + tid * 4);
    float4 b4 = *(const float4*)(b + tid * 4);
    float o[4];
    o[0]=(f.x-mean)*r*g4.x+b4.x; o[1]=(f.y-mean)*r*g4.y+b4.y;
    o[2]=(f.z-mean)*r*g4.z+b4.z; o[3]=(f.w-mean)*r*g4.w+b4.w;
    size_t base = (size_t)row * D_ + tid * 4;
#pragma unroll
    for (int j = 0; j < 4; j += 2)
        *(__half2*)(y + base + j) = __halves2half2(__float2half_rn(o[j]), __float2half_rn(o[j+1]));
}

// ---------------- fp16 mma.sync GEMM 256x128, Kc=64, SW128, x3, 512 thr ------
// C = act(A@B^T + bias) + r1 + r2
static constexpr int A_TILE = 256 * 64 * 2;     // 32 KB
static constexpr int B_TILE = 128 * 64 * 2;     // 16 KB
static constexpr int S_A = 0, S_B = A_TILE;
static constexpr int STAGEB = A_TILE + B_TILE;  // 48 KB
static constexpr int GEMM_SMEM = 3 * STAGEB;    // 144 KB -> 1 CTA/SM

__device__ __forceinline__ void tileA_cpa(const fp16* __restrict__ g,
                                          int row0, int stride, int k0,
                                          uint32_t sdst, int tid) {
#pragma unroll
    for (int i = 0; i < 4; i++) {
        int idx = i * 512 + tid;          // 0..2047
        int r = idx >> 3, c = idx & 7;
        CPA(sdst + swz(r * 128 + c * 16), g + (size_t)(row0 + r) * stride + k0 + c * 8);
    }
}
__device__ __forceinline__ void tileB_cpa(const fp16* __restrict__ g,
                                          int row0, int stride, int k0,
                                          uint32_t sdst, int tid) {
#pragma unroll
    for (int i = 0; i < 2; i++) {
        int idx = i * 512 + tid;          // 0..1023
        int r = idx >> 3, c = idx & 7;
        CPA(sdst + swz(r * 128 + c * 16), g + (size_t)(row0 + r) * stride + k0 + c * 8);
    }
}

__global__ __launch_bounds__(512, 1) void gemm_mma_kernel(
    const fp16* __restrict__ A, const fp16* __restrict__ Bm,
    const float* __restrict__ bias, const float* __restrict__ r1,
    const float* __restrict__ r2, float* __restrict__ C,
    fp16* __restrict__ Ch, int NN, int KK, int act) {
    extern __shared__ char smem[];
    const uint32_t sb = smem_u32(smem);
    const int tid = threadIdx.x;
    const int wid = tid >> 5, lane = tid & 31;
    const int wm = wid >> 2, wn = wid & 3;        // 4 x 4 warps; warp tile 64x32
    const int rowBase = blockIdx.y * 256, colBase = blockIdx.x * 128;

    float acc[4][4][4];
#pragma unroll
    for (int i = 0; i < 4; i++)
#pragma unroll
        for (int j = 0; j < 4; j++)
#pragma unroll
            for (int q = 0; q < 4; q++) acc[i][j][q] = 0.f;

    const uint32_t a_row = (uint32_t)((wm * 64 + (lane & 15)) * 128);
    const uint32_t a_col = (uint32_t)((lane >> 4) * 16);
    const uint32_t b_row0 = (uint32_t)((wn * 32 + (lane & 7) + ((lane >> 4) << 3)) * 128);
    const uint32_t b_col = (uint32_t)(((lane >> 3) & 1) * 16);

    const int nc = KK / 64;
    tileA_cpa(A,  rowBase, KK, 0, sb + S_A, tid);
    tileB_cpa(Bm, colBase, KK, 0, sb + S_B, tid);
    CPA_COMMIT();
    {
        uint32_t st = sb + STAGEB;
        tileA_cpa(A,  rowBase, KK, 64, st + S_A, tid);
        tileB_cpa(Bm, colBase, KK, 64, st + S_B, tid);
    }
    CPA_COMMIT();

    for (int c = 0; c < nc; c++) {
        if (c + 1 < nc) CPA_WAIT1(); else CPA_WAIT0();
        __syncthreads();
        if (c + 2 < nc) {
            uint32_t st = sb + ((c + 2) % 3) * STAGEB;
            int k0 = (c + 2) * 64;
            tileA_cpa(A,  rowBase, KK, k0, st + S_A, tid);
            tileB_cpa(Bm, colBase, KK, k0, st + S_B, tid);
            CPA_COMMIT();
        }
        uint32_t st = sb + (c % 3) * STAGEB;

#pragma unroll
        for (int ks = 0; ks < 4; ks++) {
            const uint32_t kb = ks * 32;
            uint32_t bh[2][4];
#pragma unroll
            for (int g = 0; g < 2; g++) {
                uint32_t roff = b_row0 + (uint32_t)(g * 16 * 128);
                ldsm4(bh[g], st + S_B + smx(roff, kb + b_col));
            }
#pragma unroll
            for (int mi = 0; mi < 4; mi++) {
                uint32_t roff = a_row + (uint32_t)(mi * 16 * 128);
                uint32_t af[4];
                ldsm4(af, st + S_A + smx(roff, kb + a_col));
#pragma unroll
                for (int nj = 0; nj < 4; nj++) {
                    int g = nj >> 1, o = (nj & 1) * 2;
                    mma16816h(acc[mi][nj], af, bh[g][o], bh[g][o + 1]);
                }
            }
        }
    }

    const int tq = lane >> 2, tr = lane & 3;
#pragma unroll
    for (int mi = 0; mi < 4; mi++) {
#pragma unroll
        for (int nj = 0; nj < 4; nj++) {
            int n = colBase + wn * 32 + nj * 8 + tr * 2;
            float2 bb = *(const float2*)(bias + n);
#pragma unroll
            for (int half = 0; half < 2; half++) {
                int m = rowBase + wm * 64 + mi * 16 + tq + half * 8;
                size_t base = (size_t)m * NN + n;
                float v0 = acc[mi][nj][half * 2 + 0] + bb.x;
                float v1 = acc[mi][nj][half * 2 + 1] + bb.y;
                if (act == 1) { v0 = v0 * normcdff(v0); v1 = v1 * normcdff(v1); }
                if (r1) { float2 q = *(const float2*)(r1 + base); v0 += q.x; v1 += q.y; }
                if (r2) { float2 q = *(const float2*)(r2 + base); v0 += q.x; v1 += q.y; }
                if (C) { float2 ov = {v0, v1}; *(float2*)(C + base) = ov; }
                if (Ch)
                    *(__half2*)(Ch + base) = __halves2half2(__float2half_rn(v0), __float2half_rn(v1));
            }
        }
    }
}

// ---------------- tensor-core attention (single-plane fp16) ------------------
static constexpr int QT = 32;
static constexpr int SCS2 = 520;
static constexpr int AO_Q  = 0;
static constexpr int AO_KV = 4096;
static constexpr int AO_SC = 20480;
static constexpr int AO_AW = 87040;
static constexpr int ATTN_SMEM = 120320;

__device__ __forceinline__ void tile64_cpa(const fp16* __restrict__ g,
                                           int row0, int stride, uint32_t sdst, int tid) {
#pragma unroll
    for (int i = 0; i < 2; i++) {
        int idx = i * 256 + tid;
        int r = idx >> 3, c = idx & 7;
        CPA(sdst + swz(r * 128 + c * 16), g + (size_t)(row0 + r) * stride + c * 8);
    }
}

__global__ __launch_bounds__(256, 1) void attn_mma_kernel(
    const fp16* __restrict__ qkv, const float* __restrict__ bias,
    fp16* __restrict__ Ctx) {
    extern __shared__ char smem[];
    const uint32_t sb = smem_u32(smem);
    const int tid = threadIdx.x;
    const int wid = tid >> 5, lane = tid & 31;
    const int wm = wid >> 2, wn = wid & 3;
    const int q0 = blockIdx.x * QT, h = blockIdx.y, b = blockIdx.z;
    const size_t base3 = (size_t)(b * S_) * D3 + h * DH_;
    const fp16* Q = qkv + base3;
    const fp16* K = qkv + base3 + D_;
    const fp16* V = qkv + base3 + 2 * D_;
    const int tq = lane >> 2, tr = lane & 3;

    {
        int r = tid >> 3, c = tid & 7;
        CPA(sb + AO_Q + swz(r * 128 + c * 16), Q + (size_t)(q0 + r) * D3 + c * 8);
    }
    tile64_cpa(K, 0, D3, sb + AO_KV, tid);
    CPA_COMMIT();
    CPA_WAIT0();
    __syncthreads();

    uint32_t qf[4][4];
    {
        uint32_t arow = (uint32_t)((wm * 16 + (lane & 15)) * 128);
        uint32_t acol = (uint32_t)((lane >> 4) * 16);
#pragma unroll
        for (int ks = 0; ks < 4; ks++)
            ldsm4(qf[ks], sb + AO_Q + smx(arow, ks * 32 + acol));
    }

    const uint32_t b_row = (uint32_t)((wn * 16 + (lane & 7) + ((lane >> 4) << 3)) * 128);
    const uint32_t b_col = (uint32_t)(((lane >> 3) & 1) * 16);
    for (int c = 0; c < 8; c++) {
        if (c < 7) {
            uint32_t st = sb + AO_KV + ((c + 1) & 1) * 8192;
            tile64_cpa(K, (c + 1) * 64, D3, st, tid);
            CPA_COMMIT();
            CPA_WAIT1();
        } else {
            CPA_WAIT0();
        }
        __syncthreads();
        uint32_t st = sb + AO_KV + (c & 1) * 8192;

        float acc[2][4] = {};
#pragma unroll
        for (int ks = 0; ks < 4; ks++) {
            uint32_t kh4[4];
            ldsm4(kh4, st + smx(b_row, ks * 32 + b_col));
#pragma unroll
            for (int nj = 0; nj < 2; nj++)
                mma16816h(acc[nj], qf[ks], kh4[nj * 2], kh4[nj * 2 + 1]);
        }
        float* sc = (float*)(smem + AO_SC);
#pragma unroll
        for (int nj = 0; nj < 2; nj++) {
            int kg = c * 64 + wn * 16 + nj * 8 + tr * 2;
#pragma unroll
            for (int half = 0; half < 2; half++) {
                int m = wm * 16 + tq + half * 8;
                int rel = (q0 + m) - kg + (P_ - 1);
                sc[m * SCS2 + kg]     = acc[nj][half*2+0] * 0.125f + __ldg(&bias[rel * H_ + h]);
                sc[m * SCS2 + kg + 1] = acc[nj][half*2+1] * 0.125f + __ldg(&bias[(rel - 1) * H_ + h]);
            }
        }
        __syncthreads();
    }

    tile64_cpa(V, 0, D3, sb + AO_KV, tid);
    CPA_COMMIT();

    {
        float* sc = (float*)(smem + AO_SC);
        fp16* aw = (fp16*)(smem + AO_AW);
#pragma unroll
        for (int rr = 0; rr < 4; rr++) {
            int r = wid * 4 + rr;
            float* row = sc + r * SCS2;
            float mx = -1e30f;
            for (int cc = lane; cc < S_; cc += 32) mx = fmaxf(mx, row[cc]);
#pragma unroll
            for (int o = 16; o > 0; o >>= 1) mx = fmaxf(mx, __shfl_xor_sync(0xffffffffu, mx, o));
            float sum = 0.f;
            for (int cc = lane; cc < S_; cc += 32) {
                float e = expf(row[cc] - mx);
                row[cc] = e;
                sum += e;
            }
#pragma unroll
            for (int o = 16; o > 0; o >>= 1) sum += __shfl_xor_sync(0xffffffffu, sum, o);
            float inv = 1.0f / sum;
            for (int cc = lane; cc < S_; cc += 32)
                aw[r * SCS2 + cc] = __float2half_rn(row[cc] * inv);
        }
    }
    __syncthreads();

    float cacc[2][4] = {};
    const uint32_t aw_row = (uint32_t)((wm * 16 + (lane & 15)) * (SCS2 * 2));
    const uint32_t v_row = (uint32_t)(((lane & 7) + ((lane >> 3) & 1) * 8) * 128);
    const uint32_t v_col = (uint32_t)(wn * 32 + (lane >> 4) * 16);
    for (int c = 0; c < 8; c++) {
        if (c < 7) {
            uint32_t st = sb + AO_KV + ((c + 1) & 1) * 8192;
            tile64_cpa(V, (c + 1) * 64, D3, st, tid);
            CPA_COMMIT();
            CPA_WAIT1();
        } else {
            CPA_WAIT0();
        }
        __syncthreads();
        uint32_t st = sb + AO_KV + (c & 1) * 8192;

#pragma unroll
        for (int ks = 0; ks < 4; ks++) {
            uint32_t awoff = aw_row + (uint32_t)((c * 64 + ks * 16 + (lane >> 4) * 8) * 2);
            uint32_t ah4[4];
            ldsm4(ah4, sb + AO_AW + awoff);
            uint32_t vh4[4];
            ldsm4t(vh4, st + smx(v_row + (uint32_t)(ks * 16 * 128), v_col));
#pragma unroll
            for (int nj = 0; nj < 2; nj++)
                mma16816h(cacc[nj], ah4, vh4[nj * 2], vh4[nj * 2 + 1]);
        }
        __syncthreads();
    }

#pragma unroll
    for (int nj = 0; nj < 2; nj++) {
        int n = wn * 16 + nj * 8 + tr * 2;
#pragma unroll
        for (int half = 0; half < 2; half++) {
            int m = wm * 16 + tq + half * 8;
            size_t gidx = (size_t)(b * S_ + q0 + m) * D_ + h * DH_ + n;
            *(__half2*)(Ctx + gidx) = __halves2half2(
                __float2half_rn(cacc[nj][half*2+0]), __float2half_rn(cacc[nj][half*2+1]));
        }
    }
}

// ---------------- launch ----------------------------------------------------
extern "C" void kernel_launch(void* const* d_in, const int* in_sizes, int n_in,
                              void* d_out, int out_size) {
    (void)in_sizes; (void)n_in; (void)out_size;
    const float* x    = (const float*)d_in[0];
    const float* pe   = (const float*)d_in[1];
    const float* wq   = (const float*)d_in[2];
    const float* bq   = (const float*)d_in[3];
    const float* wk   = (const float*)d_in[4];
    const float* bk   = (const float*)d_in[5];
    const float* wv   = (const float*)d_in[6];
    const float* bv   = (const float*)d_in[7];
    const float* wo   = (const float*)d_in[8];
    const float* bo   = (const float*)d_in[9];
    const float* bt   = (const float*)d_in[10];
    const float* w1   = (const float*)d_in[11];
    const float* b1   = (const float*)d_in[12];
    const float* w2   = (const float*)d_in[13];
    const float* b2   = (const float*)d_in[14];
    const float* ln1g = (const float*)d_in[15];
    const float* ln1b = (const float*)d_in[16];
    const float* ln2g = (const float*)d_in[17];
    const float* ln2b = (const float*)d_in[18];
    float* out = (float*)d_out;

    float *hb, *o1, *bqkv;
    fp16 *xn, *qkv, *cx, *f1, *wqkvp, *wop, *w1p, *w2p;
    cudaGetSymbolAddress((void**)&hb,   g_h);
    cudaGetSymbolAddress((void**)&o1,   g_out1);
    cudaGetSymbolAddress((void**)&bqkv, g_bqkv);
    cudaGetSymbolAddress((void**)&xn,   g_xn);
    cudaGetSymbolAddress((void**)&qkv,  g_qkv);
    cudaGetSymbolAddress((void**)&cx,   g_ctx);
    cudaGetSymbolAddress((void**)&f1,   g_f1);
    cudaGetSymbolAddress((void**)&wqkvp, g_wqkvT);
    cudaGetSymbolAddress((void**)&wop,  g_woT);
    cudaGetSymbolAddress((void**)&w1p,  g_w1T);
    cudaGetSymbolAddress((void**)&w2p,  g_w2T);

    cudaFuncSetAttribute(attn_mma_kernel, cudaFuncAttributeMaxDynamicSharedMemorySize, ATTN_SMEM);
    cudaFuncSetAttribute(gemm_mma_kernel, cudaFuncAttributeMaxDynamicSharedMemorySize, GEMM_SMEM);

    dim3 gQKV(D3 / 128, M_ / 256);   // (24, 32)
    dim3 gD(D_ / 128, M_ / 256);     // (8, 32)
    dim3 gF(F_ / 128, M_ / 256);     // (32, 32)
    dim3 gAttn(S_ / QT, H_, B_);

    addpe_kernel<<<(M_ * D_) / 256, 256>>>(x, pe, hb);
    packb_kernel<<<dim3(D_ / 256, L_), 256>>>(bq, bk, bv, bqkv);
    wtransqkv_kernel<<<dim3(32, 32, 3 * L_), 256>>>(wq, wk, wv, wqkvp);
    wtrans_kernel<<<dim3(32, 32, L_), 256>>>(wo, wop, D_, D_, (size_t)D_ * D_);
    wtrans_kernel<<<dim3(F_ / 32, D_ / 32, L_), 256>>>(w1, w1p, D_, F_, (size_t)D_ * F_);
    wtrans_kernel<<<dim3(D_ / 32, F_ / 32, L_), 256>>>(w2, w2p, F_, D_, (size_t)F_ * D_);

    for (int l = 0; l < L_; l++) {
        size_t oQKV = (size_t)l * D3 * D_;
        size_t oDD  = (size_t)l * D_ * D_;
        size_t oDF  = (size_t)l * D_ * F_;
        size_t oD   = (size_t)l * D_;
        size_t oF   = (size_t)l * F_;

        ln_kernel<<<M_, 256>>>(hb, ln1g + oD, ln1b + oD, xn);
        gemm_mma_kernel<<<gQKV, 512, GEMM_SMEM>>>(xn, wqkvp + oQKV,
            bqkv + (size_t)l * D3, nullptr, nullptr, nullptr, qkv, D3, D_, 0);

        attn_mma_kernel<<<gAttn, 256, ATTN_SMEM>>>(qkv,
            bt + (size_t)l * (2 * P_ - 1) * H_, cx);

        gemm_mma_kernel<<<gD, 512, GEMM_SMEM>>>(cx, wop + oDD,
            bo + oD, hb, nullptr, o1, nullptr, D_, D_, 0);

        ln_kernel<<<M_, 256>>>(o1, ln2g + oD, ln2b + oD, xn);
        gemm_mma_kernel<<<gF, 512, GEMM_SMEM>>>(xn, w1p + oDF,
            b1 + oF, nullptr, nullptr, nullptr, f1, F_, D_, 1);
        float* dst = (l == L_ - 1) ? out : hb;
        gemm_mma_kernel<<<gD, 512, GEMM_SMEM>>>(f1, w2p + oDF,
            b2 + oD, o1, hb, dst, nullptr, D_, F_, 0);
    }
}